// round 11
// baseline (speedup 1.0000x reference)
#include <cuda_runtime.h>
#include <cuda_bf16.h>
#include <math.h>

#define N_NODES   100000
#define N_EDGES   1600000
#define N_GRAPHS  256
#define IN_DIM    64
#define HID       128
#define RELU_COEF 0.05f

typedef unsigned long long ull;
typedef unsigned int uint32;

// ---------------- scratch (no allocation allowed) ----------------
__device__ float  g_agg1[(size_t)N_NODES * IN_DIM];
__device__ float  g_agg2[(size_t)N_NODES * HID];
__device__ float  g_h1  [(size_t)N_NODES * HID];
__device__ float  g_h2  [(size_t)N_NODES * HID];
__device__ uint32 g_xb  [(size_t)N_NODES * IN_DIM / 2];   // x as bf16x2
__device__ uint32 g_h1b [(size_t)N_NODES * HID / 2];      // h1 as bf16x2
__device__ float  g_pool[N_GRAPHS * HID];
__device__ int    g_deg   [N_NODES];
__device__ int    g_rowptr[N_NODES];
__device__ int    g_fill  [N_NODES];
__device__ int2   g_epak  [N_EDGES];    // (src, bits(w)) sorted by dst
__device__ int    g_blksum[512];

__device__ __forceinline__ float lrelu(float v) {
    return v > 0.f ? v : RELU_COEF * v;
}

// packed f32x2 helpers (sm_100+): 2 fp32 FMAs per issue, bit-exact fp32
#define FMA2(acc, a, b) asm("fma.rn.f32x2 %0, %1, %2, %0;" : "+l"(acc) : "l"(a), "l"(b))
#define PACK2(d, x)     asm("mov.b64 %0, {%1, %1};" : "=l"(d) : "f"(x))
#define UNPACK2(lo, hi, v) asm("mov.b64 {%0, %1}, %2;" : "=f"(lo), "=f"(hi) : "l"(v))

__device__ __forceinline__ uint32 pack_bf2(float a, float b) {
    __nv_bfloat162 h = __floats2bfloat162_rn(a, b);
    return *reinterpret_cast<uint32*>(&h);
}
__device__ __forceinline__ float2 unpack_bf2(uint32 v) {
    __nv_bfloat162 h = *reinterpret_cast<__nv_bfloat162*>(&v);
    return __bfloat1622float2(h);
}

// ---------------- small utility kernels ----------------
__global__ void zero_f4_kernel(float4* p, int n4) {
    int i = blockIdx.x * blockDim.x + threadIdx.x;
    if (i < n4) p[i] = make_float4(0.f, 0.f, 0.f, 0.f);
}
__global__ void zero_int_kernel(int* p, int n) {
    int i = blockIdx.x * blockDim.x + threadIdx.x;
    if (i < n) p[i] = 0;
}
__global__ void tobf16_kernel(const float2* __restrict__ in, uint32* __restrict__ out, int n2) {
    int i = blockIdx.x * blockDim.x + threadIdx.x;
    if (i < n2) {
        float2 v = in[i];
        out[i] = pack_bf2(v.x, v.y);
    }
}

// ---------------- CSR build: histogram / scan / fill ----------------
__global__ void hist_kernel(const int* __restrict__ dst, int* __restrict__ deg) {
    int e = blockIdx.x * blockDim.x + threadIdx.x;
    if (e < N_EDGES) atomicAdd(&deg[dst[e]], 1);
}
__global__ void scan1_kernel(const int* __restrict__ deg, int* __restrict__ rowptr,
                             int* __restrict__ blksum) {
    __shared__ int s[256];
    int i = blockIdx.x * 256 + threadIdx.x;
    int v = (i < N_NODES) ? deg[i] : 0;
    s[threadIdx.x] = v;
    __syncthreads();
    for (int off = 1; off < 256; off <<= 1) {
        int t = 0;
        if (threadIdx.x >= off) t = s[threadIdx.x - off];
        __syncthreads();
        s[threadIdx.x] += t;
        __syncthreads();
    }
    if (i < N_NODES) rowptr[i] = s[threadIdx.x] - v;    // exclusive
    if (threadIdx.x == 255) blksum[blockIdx.x] = s[255];
}
__global__ void scan2_kernel(int* blksum, int nblk) {
    __shared__ int s[512];
    int t = threadIdx.x;
    int v = (t < nblk) ? blksum[t] : 0;
    s[t] = v;
    __syncthreads();
    for (int off = 1; off < 512; off <<= 1) {
        int u = (t >= off) ? s[t - off] : 0;
        __syncthreads();
        s[t] += u;
        __syncthreads();
    }
    if (t < nblk) blksum[t] = s[t] - v;   // exclusive
}
__global__ void scan3_kernel(int* __restrict__ rowptr, int* __restrict__ fill,
                             const int* __restrict__ blksum) {
    int i = blockIdx.x * 256 + threadIdx.x;
    if (i < N_NODES) {
        int r = rowptr[i] + blksum[blockIdx.x];
        rowptr[i] = r;
        fill[i] = r;
    }
}
__global__ void fill_kernel(const int* __restrict__ src, const int* __restrict__ dst,
                            const float* __restrict__ w, int* __restrict__ fill,
                            int2* __restrict__ epak) {
    int e = blockIdx.x * blockDim.x + threadIdx.x;
    if (e < N_EDGES) {
        int pos = atomicAdd(&fill[dst[e]], 1);
        epak[pos] = make_int2(src[e], __float_as_int(w[e]));
    }
}

// ---------------- gather aggregation (bf16 input): warp per node ---------
template<int D>
__global__ void __launch_bounds__(256)
gather_kernel(const uint32* __restrict__ xb, const int* __restrict__ rowptr,
              const int* __restrict__ deg, const int2* __restrict__ epak,
              float* __restrict__ agg)
{
    int warp = (blockIdx.x * blockDim.x + threadIdx.x) >> 5;
    int lane = threadIdx.x & 31;
    if (warp >= N_NODES) return;
    int start = rowptr[warp];
    int d = deg[warp];
    if (D == 128) {
        float4 acc = make_float4(0.f, 0.f, 0.f, 0.f);
        int i = 0;
        for (; i + 1 < d; i += 2) {
            int2 p0 = epak[start + i];
            int2 p1 = epak[start + i + 1];
            uint2 u0 = *(const uint2*)(xb + (size_t)p0.x * 64 + lane * 2);
            uint2 u1 = *(const uint2*)(xb + (size_t)p1.x * 64 + lane * 2);
            float w0 = __int_as_float(p0.y), w1 = __int_as_float(p1.y);
            float2 a0 = unpack_bf2(u0.x), b0 = unpack_bf2(u0.y);
            float2 a1 = unpack_bf2(u1.x), b1 = unpack_bf2(u1.y);
            acc.x += w0 * a0.x; acc.y += w0 * a0.y;
            acc.z += w0 * b0.x; acc.w += w0 * b0.y;
            acc.x += w1 * a1.x; acc.y += w1 * a1.y;
            acc.z += w1 * b1.x; acc.w += w1 * b1.y;
        }
        if (i < d) {
            int2 p = epak[start + i];
            float ww = __int_as_float(p.y);
            uint2 u = *(const uint2*)(xb + (size_t)p.x * 64 + lane * 2);
            float2 a = unpack_bf2(u.x), b = unpack_bf2(u.y);
            acc.x += ww * a.x; acc.y += ww * a.y;
            acc.z += ww * b.x; acc.w += ww * b.y;
        }
        *(float4*)(agg + (size_t)warp * 128 + lane * 4) = acc;
    } else {
        float2 acc = make_float2(0.f, 0.f);
        int i = 0;
        for (; i + 1 < d; i += 2) {
            int2 p0 = epak[start + i];
            int2 p1 = epak[start + i + 1];
            uint32 u0 = xb[(size_t)p0.x * 32 + lane];
            uint32 u1 = xb[(size_t)p1.x * 32 + lane];
            float w0 = __int_as_float(p0.y), w1 = __int_as_float(p1.y);
            float2 a0 = unpack_bf2(u0);
            float2 a1 = unpack_bf2(u1);
            acc.x += w0 * a0.x; acc.y += w0 * a0.y;
            acc.x += w1 * a1.x; acc.y += w1 * a1.y;
        }
        if (i < d) {
            int2 p = epak[start + i];
            float ww = __int_as_float(p.y);
            float2 a = unpack_bf2(xb[(size_t)p.x * 32 + lane]);
            acc.x += ww * a.x; acc.y += ww * a.y;
        }
        *(float2*)(agg + (size_t)warp * 64 + lane * 2) = acc;
    }
}

// ---------------- fused dual-input linear + leaky (f32x2 packed) -----------
// R2 dense shape; NEW: __launch_bounds__(256, 3) to lift occupancy 2->3 CTAs/SM
// (R10 ncu: regs=128 capped the sibling gate kernel at 2 CTAs, fma pipe 52%).
template<int K1, int K2>
__global__ void __launch_bounds__(256, 3)
linear2_kernel(const float* __restrict__ A1, const float* __restrict__ A2,
               const float* __restrict__ W1, const float* __restrict__ W2,
               const float* __restrict__ bias, float* __restrict__ out,
               uint32* __restrict__ out_bf)
{
    constexpr int K  = K1 + K2;
    constexpr int KC = 32;
    __shared__ float Ast[KC][64];     // transposed A tile: 8 KB
    __shared__ float Ws[KC][128];     // 16 KB
    const int n0  = blockIdx.x * 64;
    const int tid = threadIdx.x;
    const int tj  = tid & 31;
    const int tn  = tid >> 5;

    ull acc[4][4];
#pragma unroll
    for (int p = 0; p < 4; p++)
#pragma unroll
        for (int c = 0; c < 4; c++) acc[p][c] = 0ULL;

    for (int kc = 0; kc < K; kc += KC) {
#pragma unroll
        for (int r = 0; r < 2; r++) {
            int i  = tid + r * 256;
            int n  = i >> 3;
            int k4 = (i & 7) << 2;
            int gn = n0 + n, gk = kc + k4;
            float4 v = make_float4(0.f, 0.f, 0.f, 0.f);
            if (gn < N_NODES) {
                const float* p = (gk < K1) ? (A1 + (size_t)gn * K1 + gk)
                                           : (A2 + (size_t)gn * K2 + (gk - K1));
                v = *(const float4*)p;
            }
            Ast[k4 + 0][n] = v.x; Ast[k4 + 1][n] = v.y;
            Ast[k4 + 2][n] = v.z; Ast[k4 + 3][n] = v.w;
        }
#pragma unroll
        for (int r = 0; r < 4; r++) {
            int i  = tid + r * 256;
            int k  = i >> 5;
            int j4 = (i & 31) << 2;
            int gk = kc + k;
            const float* p = (gk < K1) ? (W1 + (size_t)gk * 128 + j4)
                                       : (W2 + (size_t)(gk - K1) * 128 + j4);
            *(float4*)&Ws[k][j4] = *(const float4*)p;
        }
        __syncthreads();
#pragma unroll 8
        for (int k = 0; k < KC; k++) {
            float4 w4 = *(const float4*)&Ws[k][tj << 2];
            ull wd0, wd1, wd2, wd3;
            PACK2(wd0, w4.x); PACK2(wd1, w4.y); PACK2(wd2, w4.z); PACK2(wd3, w4.w);
            const ull* ap = (const ull*)&Ast[k][tn << 3];
            ull a0 = ap[0], a1 = ap[1], a2 = ap[2], a3 = ap[3];
            FMA2(acc[0][0], a0, wd0); FMA2(acc[0][1], a0, wd1);
            FMA2(acc[0][2], a0, wd2); FMA2(acc[0][3], a0, wd3);
            FMA2(acc[1][0], a1, wd0); FMA2(acc[1][1], a1, wd1);
            FMA2(acc[1][2], a1, wd2); FMA2(acc[1][3], a1, wd3);
            FMA2(acc[2][0], a2, wd0); FMA2(acc[2][1], a2, wd1);
            FMA2(acc[2][2], a2, wd2); FMA2(acc[2][3], a2, wd3);
            FMA2(acc[3][0], a3, wd0); FMA2(acc[3][1], a3, wd1);
            FMA2(acc[3][2], a3, wd2); FMA2(acc[3][3], a3, wd3);
        }
        __syncthreads();
    }
    float4 bv = *(const float4*)(bias + (tj << 2));
#pragma unroll
    for (int p = 0; p < 4; p++) {
        float lo[4], hi[4];
#pragma unroll
        for (int c = 0; c < 4; c++) UNPACK2(lo[c], hi[c], acc[p][c]);
        int nA = n0 + (tn << 3) + 2 * p;
        if (nA < N_NODES) {
            float4 r;
            r.x = lrelu(lo[0] + bv.x); r.y = lrelu(lo[1] + bv.y);
            r.z = lrelu(lo[2] + bv.z); r.w = lrelu(lo[3] + bv.w);
            *(float4*)(out + (size_t)nA * 128 + (tj << 2)) = r;
            if (out_bf) {
                uint2 u;
                u.x = pack_bf2(r.x, r.y);
                u.y = pack_bf2(r.z, r.w);
                *(uint2*)(out_bf + (size_t)nA * 64 + (tj << 1)) = u;
            }
        }
        if (nA + 1 < N_NODES) {
            float4 r;
            r.x = lrelu(hi[0] + bv.x); r.y = lrelu(hi[1] + bv.y);
            r.z = lrelu(hi[2] + bv.z); r.w = lrelu(hi[3] + bv.w);
            *(float4*)(out + (size_t)(nA + 1) * 128 + (tj << 2)) = r;
            if (out_bf) {
                uint2 u;
                u.x = pack_bf2(r.x, r.y);
                u.y = pack_bf2(r.z, r.w);
                *(uint2*)(out_bf + (size_t)(nA + 1) * 64 + (tj << 1)) = u;
            }
        }
    }
}

// ---------------- fused gate + graph pooling (f32x2 packed) ----------------
// R2 shape + __launch_bounds__(256, 3).
__global__ void __launch_bounds__(256, 3)
gate_pool_kernel(const float* __restrict__ h2, const float* __restrict__ x0,
                 const float* __restrict__ Wsig, const float* __restrict__ Wtanh,
                 const float* __restrict__ bsig, const float* __restrict__ btanh,
                 const int*   __restrict__ batch, float* __restrict__ pool)
{
    constexpr int K1 = HID;
    constexpr int K2 = IN_DIM;
    constexpr int K  = K1 + K2;   // 192
    constexpr int KC = 32;
    __shared__ float Ast[KC][64];   // 8 KB
    __shared__ float WsS[KC][128];  // 16 KB
    __shared__ float WsT[KC][128];  // 16 KB
    const int n0  = blockIdx.x * 64;
    const int tid = threadIdx.x;
    const int tj  = tid & 31;
    const int tn  = tid >> 5;

    ull accS[4][4], accT[4][4];
#pragma unroll
    for (int p = 0; p < 4; p++)
#pragma unroll
        for (int c = 0; c < 4; c++) { accS[p][c] = 0ULL; accT[p][c] = 0ULL; }

    for (int kc = 0; kc < K; kc += KC) {
#pragma unroll
        for (int r = 0; r < 2; r++) {
            int i  = tid + r * 256;
            int n  = i >> 3;
            int k4 = (i & 7) << 2;
            int gn = n0 + n, gk = kc + k4;
            float4 v = make_float4(0.f, 0.f, 0.f, 0.f);
            if (gn < N_NODES) {
                const float* p = (gk < K1) ? (h2 + (size_t)gn * K1 + gk)
                                           : (x0 + (size_t)gn * K2 + (gk - K1));
                v = *(const float4*)p;
            }
            Ast[k4 + 0][n] = v.x; Ast[k4 + 1][n] = v.y;
            Ast[k4 + 2][n] = v.z; Ast[k4 + 3][n] = v.w;
        }
#pragma unroll
        for (int r = 0; r < 4; r++) {
            int i  = tid + r * 256;
            int k  = i >> 5;
            int j4 = (i & 31) << 2;
            int gk = kc + k;
            *(float4*)&WsS[k][j4] = *(const float4*)(Wsig  + (size_t)gk * 128 + j4);
            *(float4*)&WsT[k][j4] = *(const float4*)(Wtanh + (size_t)gk * 128 + j4);
        }
        __syncthreads();
#pragma unroll 4
        for (int k = 0; k < KC; k++) {
            const ull* ap = (const ull*)&Ast[k][tn << 3];
            ull a0 = ap[0], a1 = ap[1], a2 = ap[2], a3 = ap[3];
            {
                float4 w4 = *(const float4*)&WsS[k][tj << 2];
                ull w0, w1, w2, w3;
                PACK2(w0, w4.x); PACK2(w1, w4.y); PACK2(w2, w4.z); PACK2(w3, w4.w);
                FMA2(accS[0][0], a0, w0); FMA2(accS[0][1], a0, w1);
                FMA2(accS[0][2], a0, w2); FMA2(accS[0][3], a0, w3);
                FMA2(accS[1][0], a1, w0); FMA2(accS[1][1], a1, w1);
                FMA2(accS[1][2], a1, w2); FMA2(accS[1][3], a1, w3);
                FMA2(accS[2][0], a2, w0); FMA2(accS[2][1], a2, w1);
                FMA2(accS[2][2], a2, w2); FMA2(accS[2][3], a2, w3);
                FMA2(accS[3][0], a3, w0); FMA2(accS[3][1], a3, w1);
                FMA2(accS[3][2], a3, w2); FMA2(accS[3][3], a3, w3);
            }
            {
                float4 w4 = *(const float4*)&WsT[k][tj << 2];
                ull w0, w1, w2, w3;
                PACK2(w0, w4.x); PACK2(w1, w4.y); PACK2(w2, w4.z); PACK2(w3, w4.w);
                FMA2(accT[0][0], a0, w0); FMA2(accT[0][1], a0, w1);
                FMA2(accT[0][2], a0, w2); FMA2(accT[0][3], a0, w3);
                FMA2(accT[1][0], a1, w0); FMA2(accT[1][1], a1, w1);
                FMA2(accT[1][2], a1, w2); FMA2(accT[1][3], a1, w3);
                FMA2(accT[2][0], a2, w0); FMA2(accT[2][1], a2, w1);
                FMA2(accT[2][2], a2, w2); FMA2(accT[2][3], a2, w3);
                FMA2(accT[3][0], a3, w0); FMA2(accT[3][1], a3, w1);
                FMA2(accT[3][2], a3, w2); FMA2(accT[3][3], a3, w3);
            }
        }
        __syncthreads();
    }

    float4 bs = *(const float4*)(bsig  + (tj << 2));
    float4 bt = *(const float4*)(btanh + (tj << 2));

    float vS[8][4], vT[8][4];
#pragma unroll
    for (int p = 0; p < 4; p++)
#pragma unroll
        for (int c = 0; c < 4; c++) {
            UNPACK2(vS[2 * p][c], vS[2 * p + 1][c], accS[p][c]);
            UNPACK2(vT[2 * p][c], vT[2 * p + 1][c], accT[p][c]);
        }

    const float bsa[4] = {bs.x, bs.y, bs.z, bs.w};
    const float bta[4] = {bt.x, bt.y, bt.z, bt.w};

    // run-length compress consecutive nodes with same batch id (batch sorted)
    int curb = -1;
    float s[4] = {0.f, 0.f, 0.f, 0.f};
#pragma unroll
    for (int nn = 0; nn < 8; nn++) {
        int n = n0 + (tn << 3) + nn;
        if (n >= N_NODES) break;
        int b = batch[n];
        float v[4];
#pragma unroll
        for (int c = 0; c < 4; c++) {
            float sx = fminf(fmaxf(vS[nn][c] + bsa[c], -30.f), 30.f);
            v[c] = tanhf(vT[nn][c] + bta[c]) / (1.f + expf(sx));
        }
        if (b != curb) {
            if (curb >= 0) {
                float* pp = pool + (size_t)curb * 128 + (tj << 2);
                atomicAdd(pp + 0, s[0]); atomicAdd(pp + 1, s[1]);
                atomicAdd(pp + 2, s[2]); atomicAdd(pp + 3, s[3]);
            }
            curb = b;
            s[0] = v[0]; s[1] = v[1]; s[2] = v[2]; s[3] = v[3];
        } else {
            s[0] += v[0]; s[1] += v[1]; s[2] += v[2]; s[3] += v[3];
        }
    }
    if (curb >= 0) {
        float* pp = pool + (size_t)curb * 128 + (tj << 2);
        atomicAdd(pp + 0, s[0]); atomicAdd(pp + 1, s[1]);
        atomicAdd(pp + 2, s[2]); atomicAdd(pp + 3, s[3]);
    }
}

// ---------------- head MLP: one block per graph ----------------
__global__ void __launch_bounds__(256)
head_kernel(const float* __restrict__ pool,
            const float* __restrict__ Wf1, const float* __restrict__ bf1,
            const float* __restrict__ Wf2, const float* __restrict__ bf2,
            const float* __restrict__ Wout, const float* __restrict__ bout,
            float* __restrict__ out)
{
    __shared__ float p[128], f1[128], f2[258], red[256];
    const int g = blockIdx.x, tid = threadIdx.x;
    if (tid < 128) p[tid] = pool[(size_t)g * 128 + tid];
    __syncthreads();
    if (tid < 128) {
        float s = bf1[tid];
#pragma unroll 8
        for (int k = 0; k < 128; k++) s += p[k] * Wf1[k * 128 + tid];
        f1[tid] = lrelu(s);
    }
    __syncthreads();
    for (int j = tid; j < 258; j += 256) {
        float s = bf2[j];
#pragma unroll 8
        for (int k = 0; k < 128; k++) s += f1[k] * Wf2[k * 258 + j];
        f2[j] = lrelu(s);
    }
    __syncthreads();
    float s = 0.f;
    for (int k = tid; k < 258; k += 256) s += f2[k] * Wout[k];
    red[tid] = s;
    __syncthreads();
    for (int off = 128; off > 0; off >>= 1) {
        if (tid < off) red[tid] += red[tid + off];
        __syncthreads();
    }
    if (tid == 0) {
        float v = red[0] + bout[0];
        out[g] = 1.f / (1.f + expf(-v));
    }
}

// ---------------- launch ----------------
extern "C" void kernel_launch(void* const* d_in, const int* in_sizes, int n_in,
                              void* d_out, int out_size)
{
    const float* x      = (const float*)d_in[0];
    const int*   ei     = (const int*)  d_in[1];
    const int*   batch  = (const int*)  d_in[2];
    const float* eattr  = (const float*)d_in[3];
    const float* Wrel1  = (const float*)d_in[4];
    const float* brel1  = (const float*)d_in[5];
    const float* Wroot1 = (const float*)d_in[6];
    const float* Wrel2  = (const float*)d_in[7];
    const float* brel2  = (const float*)d_in[8];
    const float* Wroot2 = (const float*)d_in[9];
    const float* Wsig   = (const float*)d_in[10];
    const float* bsig   = (const float*)d_in[11];
    const float* Wtanh  = (const float*)d_in[12];
    const float* btanh  = (const float*)d_in[13];
    const float* Wf1    = (const float*)d_in[14];
    const float* bf1    = (const float*)d_in[15];
    const float* Wf2    = (const float*)d_in[16];
    const float* bf2    = (const float*)d_in[17];
    const float* Wout   = (const float*)d_in[18];
    const float* bout   = (const float*)d_in[19];
    float* out = (float*)d_out;

    const int* src = ei;
    const int* dst = ei + N_EDGES;

    float *agg1, *agg2, *h1, *h2, *pool;
    uint32 *xb, *h1b;
    int *deg, *rowptr, *fill, *blksum;
    int2 *epak;
    cudaGetSymbolAddress((void**)&agg1,   g_agg1);
    cudaGetSymbolAddress((void**)&agg2,   g_agg2);
    cudaGetSymbolAddress((void**)&h1,     g_h1);
    cudaGetSymbolAddress((void**)&h2,     g_h2);
    cudaGetSymbolAddress((void**)&xb,     g_xb);
    cudaGetSymbolAddress((void**)&h1b,    g_h1b);
    cudaGetSymbolAddress((void**)&pool,   g_pool);
    cudaGetSymbolAddress((void**)&deg,    g_deg);
    cudaGetSymbolAddress((void**)&rowptr, g_rowptr);
    cudaGetSymbolAddress((void**)&fill,   g_fill);
    cudaGetSymbolAddress((void**)&epak,   g_epak);
    cudaGetSymbolAddress((void**)&blksum, g_blksum);

    const int nodeBlocks = (N_NODES + 63) / 64;
    const int scanBlocks = (N_NODES + 255) / 256;   // 391
    const int edgeBlocks = (N_EDGES + 255) / 256;

    // ---- CSR build (shared by both layers) + x -> bf16 ----
    zero_int_kernel<<<scanBlocks, 256>>>(deg, N_NODES);
    hist_kernel<<<edgeBlocks, 256>>>(dst, deg);
    scan1_kernel<<<scanBlocks, 256>>>(deg, rowptr, blksum);
    scan2_kernel<<<1, 512>>>(blksum, scanBlocks);
    scan3_kernel<<<scanBlocks, 256>>>(rowptr, fill, blksum);
    fill_kernel<<<edgeBlocks, 256>>>(src, dst, eattr, fill, epak);
    {
        int n2 = N_NODES * IN_DIM / 2;
        tobf16_kernel<<<(n2 + 255) / 256, 256>>>((const float2*)x, xb, n2);
    }

    // ---- layer 1 ----
    gather_kernel<IN_DIM><<<(N_NODES * 32 + 255) / 256, 256>>>(xb, rowptr, deg, epak, agg1);
    linear2_kernel<IN_DIM, IN_DIM><<<nodeBlocks, 256>>>(agg1, x, Wrel1, Wroot1, brel1, h1, h1b);
    // ---- layer 2 ----
    gather_kernel<HID><<<(N_NODES * 32 + 255) / 256, 256>>>(h1b, rowptr, deg, epak, agg2);
    linear2_kernel<HID, HID><<<nodeBlocks, 256>>>(agg2, h1, Wrel2, Wroot2, brel2, h2, (uint32*)0);
    // ---- gate + pool ----
    {
        int n4 = N_GRAPHS * HID / 4;
        zero_f4_kernel<<<(n4 + 255) / 256, 256>>>((float4*)pool, n4);
        gate_pool_kernel<<<nodeBlocks, 256>>>(h2, x, Wsig, Wtanh, bsig, btanh, batch, pool);
    }
    // ---- head ----
    head_kernel<<<N_GRAPHS, 256>>>(pool, Wf1, bf1, Wf2, bf2, Wout, bout, out);
}

// round 13
// speedup vs baseline: 1.1238x; 1.1238x over previous
#include <cuda_runtime.h>
#include <cuda_bf16.h>
#include <math.h>

#define N_NODES   100000
#define N_EDGES   1600000
#define N_GRAPHS  256
#define IN_DIM    64
#define HID       128
#define RELU_COEF 0.05f

typedef unsigned long long ull;
typedef unsigned int uint32;

// ---------------- scratch (no allocation allowed) ----------------
__device__ float  g_h1  [(size_t)N_NODES * HID];
__device__ float  g_h2  [(size_t)N_NODES * HID];
__device__ uint32 g_xb  [(size_t)N_NODES * IN_DIM / 2];   // x as bf16x2
__device__ uint32 g_h1b [(size_t)N_NODES * HID / 2];      // h1 as bf16x2
__device__ float  g_pool[N_GRAPHS * HID];
__device__ int    g_deg   [N_NODES];
__device__ int    g_rowptr[N_NODES];
__device__ int    g_fill  [N_NODES];
__device__ int2   g_epak  [N_EDGES];    // (src, bits(w)) sorted by dst
__device__ int    g_blksum[512];

__device__ __forceinline__ float lrelu(float v) {
    return v > 0.f ? v : RELU_COEF * v;
}

// packed f32x2 helpers (sm_100+): 2 fp32 FMAs per issue, bit-exact fp32
#define FMA2(acc, a, b) asm("fma.rn.f32x2 %0, %1, %2, %0;" : "+l"(acc) : "l"(a), "l"(b))
#define PACK2(d, x)     asm("mov.b64 %0, {%1, %1};" : "=l"(d) : "f"(x))
#define UNPACK2(lo, hi, v) asm("mov.b64 {%0, %1}, %2;" : "=f"(lo), "=f"(hi) : "l"(v))

__device__ __forceinline__ uint32 pack_bf2(float a, float b) {
    __nv_bfloat162 h = __floats2bfloat162_rn(a, b);
    return *reinterpret_cast<uint32*>(&h);
}
__device__ __forceinline__ float2 unpack_bf2(uint32 v) {
    __nv_bfloat162 h = *reinterpret_cast<__nv_bfloat162*>(&v);
    return __bfloat1622float2(h);
}

// ---------------- small utility kernels ----------------
__global__ void zero_f4_kernel(float4* p, int n4) {
    int i = blockIdx.x * blockDim.x + threadIdx.x;
    if (i < n4) p[i] = make_float4(0.f, 0.f, 0.f, 0.f);
}
__global__ void zero_int_kernel(int* p, int n) {
    int i = blockIdx.x * blockDim.x + threadIdx.x;
    if (i < n) p[i] = 0;
}
__global__ void tobf16_kernel(const float2* __restrict__ in, uint32* __restrict__ out, int n2) {
    int i = blockIdx.x * blockDim.x + threadIdx.x;
    if (i < n2) {
        float2 v = in[i];
        out[i] = pack_bf2(v.x, v.y);
    }
}

// ---------------- CSR build: histogram / scan / fill ----------------
__global__ void hist_kernel(const int* __restrict__ dst, int* __restrict__ deg) {
    int e = blockIdx.x * blockDim.x + threadIdx.x;
    if (e < N_EDGES) atomicAdd(&deg[dst[e]], 1);
}
__global__ void scan1_kernel(const int* __restrict__ deg, int* __restrict__ rowptr,
                             int* __restrict__ blksum) {
    __shared__ int s[256];
    int i = blockIdx.x * 256 + threadIdx.x;
    int v = (i < N_NODES) ? deg[i] : 0;
    s[threadIdx.x] = v;
    __syncthreads();
    for (int off = 1; off < 256; off <<= 1) {
        int t = 0;
        if (threadIdx.x >= off) t = s[threadIdx.x - off];
        __syncthreads();
        s[threadIdx.x] += t;
        __syncthreads();
    }
    if (i < N_NODES) rowptr[i] = s[threadIdx.x] - v;    // exclusive
    if (threadIdx.x == 255) blksum[blockIdx.x] = s[255];
}
__global__ void scan2_kernel(int* blksum, int nblk) {
    __shared__ int s[512];
    int t = threadIdx.x;
    int v = (t < nblk) ? blksum[t] : 0;
    s[t] = v;
    __syncthreads();
    for (int off = 1; off < 512; off <<= 1) {
        int u = (t >= off) ? s[t - off] : 0;
        __syncthreads();
        s[t] += u;
        __syncthreads();
    }
    if (t < nblk) blksum[t] = s[t] - v;   // exclusive
}
__global__ void scan3_kernel(int* __restrict__ rowptr, int* __restrict__ fill,
                             const int* __restrict__ blksum) {
    int i = blockIdx.x * 256 + threadIdx.x;
    if (i < N_NODES) {
        int r = rowptr[i] + blksum[blockIdx.x];
        rowptr[i] = r;
        fill[i] = r;
    }
}
__global__ void fill_kernel(const int* __restrict__ src, const int* __restrict__ dst,
                            const float* __restrict__ w, int* __restrict__ fill,
                            int2* __restrict__ epak) {
    int e = blockIdx.x * blockDim.x + threadIdx.x;
    if (e < N_EDGES) {
        int pos = atomicAdd(&fill[dst[e]], 1);
        epak[pos] = make_int2(src[e], __float_as_int(w[e]));
    }
}

// ---------------- fused gather + dual-input linear + leaky ---------------
// Phase 1: warp-per-node bf16 gather of this block's 64 nodes into smem Agg.
// Phase 2: R2 dense loop, A1 read from smem Agg, A2 (root) from global.
// out[n] = lrelu( Agg[n]@Wrel + root[n]@Wroot + bias )
template<int K1, int K2>
__global__ void __launch_bounds__(256)
fused_layer_kernel(const uint32* __restrict__ xb,
                   const int* __restrict__ rowptr, const int* __restrict__ deg,
                   const int2* __restrict__ epak,
                   const float* __restrict__ Aroot,
                   const float* __restrict__ W1, const float* __restrict__ W2,
                   const float* __restrict__ bias, float* __restrict__ out,
                   uint32* __restrict__ out_bf)
{
    constexpr int K  = K1 + K2;
    constexpr int KC = 32;
    extern __shared__ char sm[];
    float (*Agg)[K1] = (float(*)[K1])sm;                               // 64*K1*4 B
    float (*Ast)[64] = (float(*)[64])(sm + 64 * K1 * 4);               // 8 KB
    float (*Ws)[128] = (float(*)[128])(sm + 64 * K1 * 4 + 8192);       // 16 KB

    const int n0  = blockIdx.x * 64;
    const int tid = threadIdx.x;
    const int wid = tid >> 5;
    const int lane = tid & 31;
    const int tj  = tid & 31;
    const int tn  = tid >> 5;

    // ---- phase 1: gather 64 nodes (8 per warp) ----
    for (int j = 0; j < 8; j++) {
        int nl = wid * 8 + j;
        int gn = n0 + nl;
        if (gn >= N_NODES) break;
        int start = rowptr[gn];
        int d = deg[gn];
        if (K1 == 128) {
            float4 acc = make_float4(0.f, 0.f, 0.f, 0.f);
            int i = 0;
            for (; i + 1 < d; i += 2) {
                int2 p0 = epak[start + i];
                int2 p1 = epak[start + i + 1];
                uint2 u0 = *(const uint2*)(xb + (size_t)p0.x * 64 + lane * 2);
                uint2 u1 = *(const uint2*)(xb + (size_t)p1.x * 64 + lane * 2);
                float w0 = __int_as_float(p0.y), w1 = __int_as_float(p1.y);
                float2 a0 = unpack_bf2(u0.x), b0 = unpack_bf2(u0.y);
                float2 a1 = unpack_bf2(u1.x), b1 = unpack_bf2(u1.y);
                acc.x += w0 * a0.x; acc.y += w0 * a0.y;
                acc.z += w0 * b0.x; acc.w += w0 * b0.y;
                acc.x += w1 * a1.x; acc.y += w1 * a1.y;
                acc.z += w1 * b1.x; acc.w += w1 * b1.y;
            }
            if (i < d) {
                int2 p = epak[start + i];
                float ww = __int_as_float(p.y);
                uint2 u = *(const uint2*)(xb + (size_t)p.x * 64 + lane * 2);
                float2 a = unpack_bf2(u.x), b = unpack_bf2(u.y);
                acc.x += ww * a.x; acc.y += ww * a.y;
                acc.z += ww * b.x; acc.w += ww * b.y;
            }
            *(float4*)&Agg[nl][lane * 4] = acc;
        } else {
            float2 acc = make_float2(0.f, 0.f);
            int i = 0;
            for (; i + 1 < d; i += 2) {
                int2 p0 = epak[start + i];
                int2 p1 = epak[start + i + 1];
                uint32 u0 = xb[(size_t)p0.x * 32 + lane];
                uint32 u1 = xb[(size_t)p1.x * 32 + lane];
                float w0 = __int_as_float(p0.y), w1 = __int_as_float(p1.y);
                float2 a0 = unpack_bf2(u0);
                float2 a1 = unpack_bf2(u1);
                acc.x += w0 * a0.x; acc.y += w0 * a0.y;
                acc.x += w1 * a1.x; acc.y += w1 * a1.y;
            }
            if (i < d) {
                int2 p = epak[start + i];
                float ww = __int_as_float(p.y);
                float2 a = unpack_bf2(xb[(size_t)p.x * 32 + lane]);
                acc.x += ww * a.x; acc.y += ww * a.y;
            }
            *(float2*)&Agg[nl][lane * 2] = acc;
        }
    }
    __syncthreads();

    // ---- phase 2: dense (R2 shape) ----
    ull acc[4][4];
#pragma unroll
    for (int p = 0; p < 4; p++)
#pragma unroll
        for (int c = 0; c < 4; c++) acc[p][c] = 0ULL;

    for (int kc = 0; kc < K; kc += KC) {
        // A tile: transposed into Ast[k][n]; source = smem Agg (k<K1) or global root
#pragma unroll
        for (int r = 0; r < 2; r++) {
            int i  = tid + r * 256;
            int n  = i >> 3;
            int k4 = (i & 7) << 2;
            int gn = n0 + n, gk = kc + k4;
            float4 v = make_float4(0.f, 0.f, 0.f, 0.f);
            if (gn < N_NODES) {
                if (gk < K1) v = *(const float4*)&Agg[n][gk];
                else         v = *(const float4*)(Aroot + (size_t)gn * K2 + (gk - K1));
            }
            Ast[k4 + 0][n] = v.x; Ast[k4 + 1][n] = v.y;
            Ast[k4 + 2][n] = v.z; Ast[k4 + 3][n] = v.w;
        }
        // W tile
#pragma unroll
        for (int r = 0; r < 4; r++) {
            int i  = tid + r * 256;
            int k  = i >> 5;
            int j4 = (i & 31) << 2;
            int gk = kc + k;
            const float* p = (gk < K1) ? (W1 + (size_t)gk * 128 + j4)
                                       : (W2 + (size_t)(gk - K1) * 128 + j4);
            *(float4*)&Ws[k][j4] = *(const float4*)p;
        }
        __syncthreads();
#pragma unroll 8
        for (int k = 0; k < KC; k++) {
            float4 w4 = *(const float4*)&Ws[k][tj << 2];
            ull wd0, wd1, wd2, wd3;
            PACK2(wd0, w4.x); PACK2(wd1, w4.y); PACK2(wd2, w4.z); PACK2(wd3, w4.w);
            const ull* ap = (const ull*)&Ast[k][tn << 3];
            ull a0 = ap[0], a1 = ap[1], a2 = ap[2], a3 = ap[3];
            FMA2(acc[0][0], a0, wd0); FMA2(acc[0][1], a0, wd1);
            FMA2(acc[0][2], a0, wd2); FMA2(acc[0][3], a0, wd3);
            FMA2(acc[1][0], a1, wd0); FMA2(acc[1][1], a1, wd1);
            FMA2(acc[1][2], a1, wd2); FMA2(acc[1][3], a1, wd3);
            FMA2(acc[2][0], a2, wd0); FMA2(acc[2][1], a2, wd1);
            FMA2(acc[2][2], a2, wd2); FMA2(acc[2][3], a2, wd3);
            FMA2(acc[3][0], a3, wd0); FMA2(acc[3][1], a3, wd1);
            FMA2(acc[3][2], a3, wd2); FMA2(acc[3][3], a3, wd3);
        }
        __syncthreads();
    }
    float4 bv = *(const float4*)(bias + (tj << 2));
#pragma unroll
    for (int p = 0; p < 4; p++) {
        float lo[4], hi[4];
#pragma unroll
        for (int c = 0; c < 4; c++) UNPACK2(lo[c], hi[c], acc[p][c]);
        int nA = n0 + (tn << 3) + 2 * p;
        if (nA < N_NODES) {
            float4 r;
            r.x = lrelu(lo[0] + bv.x); r.y = lrelu(lo[1] + bv.y);
            r.z = lrelu(lo[2] + bv.z); r.w = lrelu(lo[3] + bv.w);
            *(float4*)(out + (size_t)nA * 128 + (tj << 2)) = r;
            if (out_bf) {
                uint2 u;
                u.x = pack_bf2(r.x, r.y);
                u.y = pack_bf2(r.z, r.w);
                *(uint2*)(out_bf + (size_t)nA * 64 + (tj << 1)) = u;
            }
        }
        if (nA + 1 < N_NODES) {
            float4 r;
            r.x = lrelu(hi[0] + bv.x); r.y = lrelu(hi[1] + bv.y);
            r.z = lrelu(hi[2] + bv.z); r.w = lrelu(hi[3] + bv.w);
            *(float4*)(out + (size_t)(nA + 1) * 128 + (tj << 2)) = r;
            if (out_bf) {
                uint2 u;
                u.x = pack_bf2(r.x, r.y);
                u.y = pack_bf2(r.z, r.w);
                *(uint2*)(out_bf + (size_t)(nA + 1) * 64 + (tj << 1)) = u;
            }
        }
    }
}

// ---------------- fused gate + graph pooling (f32x2 packed, R2 shape) -----
__global__ void __launch_bounds__(256)
gate_pool_kernel(const float* __restrict__ h2, const float* __restrict__ x0,
                 const float* __restrict__ Wsig, const float* __restrict__ Wtanh,
                 const float* __restrict__ bsig, const float* __restrict__ btanh,
                 const int*   __restrict__ batch, float* __restrict__ pool)
{
    constexpr int K1 = HID;
    constexpr int K2 = IN_DIM;
    constexpr int K  = K1 + K2;   // 192
    constexpr int KC = 32;
    __shared__ float Ast[KC][64];   // 8 KB
    __shared__ float WsS[KC][128];  // 16 KB
    __shared__ float WsT[KC][128];  // 16 KB
    const int n0  = blockIdx.x * 64;
    const int tid = threadIdx.x;
    const int tj  = tid & 31;
    const int tn  = tid >> 5;

    ull accS[4][4], accT[4][4];
#pragma unroll
    for (int p = 0; p < 4; p++)
#pragma unroll
        for (int c = 0; c < 4; c++) { accS[p][c] = 0ULL; accT[p][c] = 0ULL; }

    for (int kc = 0; kc < K; kc += KC) {
#pragma unroll
        for (int r = 0; r < 2; r++) {
            int i  = tid + r * 256;
            int n  = i >> 3;
            int k4 = (i & 7) << 2;
            int gn = n0 + n, gk = kc + k4;
            float4 v = make_float4(0.f, 0.f, 0.f, 0.f);
            if (gn < N_NODES) {
                const float* p = (gk < K1) ? (h2 + (size_t)gn * K1 + gk)
                                           : (x0 + (size_t)gn * K2 + (gk - K1));
                v = *(const float4*)p;
            }
            Ast[k4 + 0][n] = v.x; Ast[k4 + 1][n] = v.y;
            Ast[k4 + 2][n] = v.z; Ast[k4 + 3][n] = v.w;
        }
#pragma unroll
        for (int r = 0; r < 4; r++) {
            int i  = tid + r * 256;
            int k  = i >> 5;
            int j4 = (i & 31) << 2;
            int gk = kc + k;
            *(float4*)&WsS[k][j4] = *(const float4*)(Wsig  + (size_t)gk * 128 + j4);
            *(float4*)&WsT[k][j4] = *(const float4*)(Wtanh + (size_t)gk * 128 + j4);
        }
        __syncthreads();
#pragma unroll 4
        for (int k = 0; k < KC; k++) {
            const ull* ap = (const ull*)&Ast[k][tn << 3];
            ull a0 = ap[0], a1 = ap[1], a2 = ap[2], a3 = ap[3];
            {
                float4 w4 = *(const float4*)&WsS[k][tj << 2];
                ull w0, w1, w2, w3;
                PACK2(w0, w4.x); PACK2(w1, w4.y); PACK2(w2, w4.z); PACK2(w3, w4.w);
                FMA2(accS[0][0], a0, w0); FMA2(accS[0][1], a0, w1);
                FMA2(accS[0][2], a0, w2); FMA2(accS[0][3], a0, w3);
                FMA2(accS[1][0], a1, w0); FMA2(accS[1][1], a1, w1);
                FMA2(accS[1][2], a1, w2); FMA2(accS[1][3], a1, w3);
                FMA2(accS[2][0], a2, w0); FMA2(accS[2][1], a2, w1);
                FMA2(accS[2][2], a2, w2); FMA2(accS[2][3], a2, w3);
                FMA2(accS[3][0], a3, w0); FMA2(accS[3][1], a3, w1);
                FMA2(accS[3][2], a3, w2); FMA2(accS[3][3], a3, w3);
            }
            {
                float4 w4 = *(const float4*)&WsT[k][tj << 2];
                ull w0, w1, w2, w3;
                PACK2(w0, w4.x); PACK2(w1, w4.y); PACK2(w2, w4.z); PACK2(w3, w4.w);
                FMA2(accT[0][0], a0, w0); FMA2(accT[0][1], a0, w1);
                FMA2(accT[0][2], a0, w2); FMA2(accT[0][3], a0, w3);
                FMA2(accT[1][0], a1, w0); FMA2(accT[1][1], a1, w1);
                FMA2(accT[1][2], a1, w2); FMA2(accT[1][3], a1, w3);
                FMA2(accT[2][0], a2, w0); FMA2(accT[2][1], a2, w1);
                FMA2(accT[2][2], a2, w2); FMA2(accT[2][3], a2, w3);
                FMA2(accT[3][0], a3, w0); FMA2(accT[3][1], a3, w1);
                FMA2(accT[3][2], a3, w2); FMA2(accT[3][3], a3, w3);
            }
        }
        __syncthreads();
    }

    float4 bs = *(const float4*)(bsig  + (tj << 2));
    float4 bt = *(const float4*)(btanh + (tj << 2));

    float vS[8][4], vT[8][4];
#pragma unroll
    for (int p = 0; p < 4; p++)
#pragma unroll
        for (int c = 0; c < 4; c++) {
            UNPACK2(vS[2 * p][c], vS[2 * p + 1][c], accS[p][c]);
            UNPACK2(vT[2 * p][c], vT[2 * p + 1][c], accT[p][c]);
        }

    const float bsa[4] = {bs.x, bs.y, bs.z, bs.w};
    const float bta[4] = {bt.x, bt.y, bt.z, bt.w};

    // run-length compress consecutive nodes with same batch id (batch sorted)
    int curb = -1;
    float s[4] = {0.f, 0.f, 0.f, 0.f};
#pragma unroll
    for (int nn = 0; nn < 8; nn++) {
        int n = n0 + (tn << 3) + nn;
        if (n >= N_NODES) break;
        int b = batch[n];
        float v[4];
#pragma unroll
        for (int c = 0; c < 4; c++) {
            float sx = fminf(fmaxf(vS[nn][c] + bsa[c], -30.f), 30.f);
            v[c] = tanhf(vT[nn][c] + bta[c]) / (1.f + expf(sx));
        }
        if (b != curb) {
            if (curb >= 0) {
                float* pp = pool + (size_t)curb * 128 + (tj << 2);
                atomicAdd(pp + 0, s[0]); atomicAdd(pp + 1, s[1]);
                atomicAdd(pp + 2, s[2]); atomicAdd(pp + 3, s[3]);
            }
            curb = b;
            s[0] = v[0]; s[1] = v[1]; s[2] = v[2]; s[3] = v[3];
        } else {
            s[0] += v[0]; s[1] += v[1]; s[2] += v[2]; s[3] += v[3];
        }
    }
    if (curb >= 0) {
        float* pp = pool + (size_t)curb * 128 + (tj << 2);
        atomicAdd(pp + 0, s[0]); atomicAdd(pp + 1, s[1]);
        atomicAdd(pp + 2, s[2]); atomicAdd(pp + 3, s[3]);
    }
}

// ---------------- head MLP: one block per graph ----------------
__global__ void __launch_bounds__(256)
head_kernel(const float* __restrict__ pool,
            const float* __restrict__ Wf1, const float* __restrict__ bf1,
            const float* __restrict__ Wf2, const float* __restrict__ bf2,
            const float* __restrict__ Wout, const float* __restrict__ bout,
            float* __restrict__ out)
{
    __shared__ float p[128], f1[128], f2[258], red[256];
    const int g = blockIdx.x, tid = threadIdx.x;
    if (tid < 128) p[tid] = pool[(size_t)g * 128 + tid];
    __syncthreads();
    if (tid < 128) {
        float s = bf1[tid];
#pragma unroll 8
        for (int k = 0; k < 128; k++) s += p[k] * Wf1[k * 128 + tid];
        f1[tid] = lrelu(s);
    }
    __syncthreads();
    for (int j = tid; j < 258; j += 256) {
        float s = bf2[j];
#pragma unroll 8
        for (int k = 0; k < 128; k++) s += f1[k] * Wf2[k * 258 + j];
        f2[j] = lrelu(s);
    }
    __syncthreads();
    float s = 0.f;
    for (int k = tid; k < 258; k += 256) s += f2[k] * Wout[k];
    red[tid] = s;
    __syncthreads();
    for (int off = 128; off > 0; off >>= 1) {
        if (tid < off) red[tid] += red[tid + off];
        __syncthreads();
    }
    if (tid == 0) {
        float v = red[0] + bout[0];
        out[g] = 1.f / (1.f + expf(-v));
    }
}

// ---------------- launch ----------------
extern "C" void kernel_launch(void* const* d_in, const int* in_sizes, int n_in,
                              void* d_out, int out_size)
{
    const float* x      = (const float*)d_in[0];
    const int*   ei     = (const int*)  d_in[1];
    const int*   batch  = (const int*)  d_in[2];
    const float* eattr  = (const float*)d_in[3];
    const float* Wrel1  = (const float*)d_in[4];
    const float* brel1  = (const float*)d_in[5];
    const float* Wroot1 = (const float*)d_in[6];
    const float* Wrel2  = (const float*)d_in[7];
    const float* brel2  = (const float*)d_in[8];
    const float* Wroot2 = (const float*)d_in[9];
    const float* Wsig   = (const float*)d_in[10];
    const float* bsig   = (const float*)d_in[11];
    const float* Wtanh  = (const float*)d_in[12];
    const float* btanh  = (const float*)d_in[13];
    const float* Wf1    = (const float*)d_in[14];
    const float* bf1    = (const float*)d_in[15];
    const float* Wf2    = (const float*)d_in[16];
    const float* bf2    = (const float*)d_in[17];
    const float* Wout   = (const float*)d_in[18];
    const float* bout   = (const float*)d_in[19];
    float* out = (float*)d_out;

    const int* src = ei;
    const int* dst = ei + N_EDGES;

    float *h1, *h2, *pool;
    uint32 *xb, *h1b;
    int *deg, *rowptr, *fill, *blksum;
    int2 *epak;
    cudaGetSymbolAddress((void**)&h1,     g_h1);
    cudaGetSymbolAddress((void**)&h2,     g_h2);
    cudaGetSymbolAddress((void**)&xb,     g_xb);
    cudaGetSymbolAddress((void**)&h1b,    g_h1b);
    cudaGetSymbolAddress((void**)&pool,   g_pool);
    cudaGetSymbolAddress((void**)&deg,    g_deg);
    cudaGetSymbolAddress((void**)&rowptr, g_rowptr);
    cudaGetSymbolAddress((void**)&fill,   g_fill);
    cudaGetSymbolAddress((void**)&epak,   g_epak);
    cudaGetSymbolAddress((void**)&blksum, g_blksum);

    const int nodeBlocks = (N_NODES + 63) / 64;
    const int scanBlocks = (N_NODES + 255) / 256;   // 391
    const int edgeBlocks = (N_EDGES + 255) / 256;
    const int SMEM_L1 = 64 * IN_DIM * 4 + 8192 + 16384;   // 40960
    const int SMEM_L2 = 64 * HID * 4 + 8192 + 16384;      // 57344

    static int attrs_set = 0;
    if (!attrs_set) {
        cudaFuncSetAttribute(fused_layer_kernel<IN_DIM, IN_DIM>,
                             cudaFuncAttributeMaxDynamicSharedMemorySize, SMEM_L1);
        cudaFuncSetAttribute(fused_layer_kernel<HID, HID>,
                             cudaFuncAttributeMaxDynamicSharedMemorySize, SMEM_L2);
        attrs_set = 1;
    }

    // ---- CSR build (shared by both layers) + x -> bf16 ----
    zero_int_kernel<<<scanBlocks, 256>>>(deg, N_NODES);
    hist_kernel<<<edgeBlocks, 256>>>(dst, deg);
    scan1_kernel<<<scanBlocks, 256>>>(deg, rowptr, blksum);
    scan2_kernel<<<1, 512>>>(blksum, scanBlocks);
    scan3_kernel<<<scanBlocks, 256>>>(rowptr, fill, blksum);
    fill_kernel<<<edgeBlocks, 256>>>(src, dst, eattr, fill, epak);
    {
        int n2 = N_NODES * IN_DIM / 2;
        tobf16_kernel<<<(n2 + 255) / 256, 256>>>((const float2*)x, xb, n2);
    }

    // ---- layer 1 (fused gather + linear) ----
    fused_layer_kernel<IN_DIM, IN_DIM><<<nodeBlocks, 256, SMEM_L1>>>(
        xb, rowptr, deg, epak, x, Wrel1, Wroot1, brel1, h1, h1b);
    // ---- layer 2 (fused gather + linear) ----
    fused_layer_kernel<HID, HID><<<nodeBlocks, 256, SMEM_L2>>>(
        h1b, rowptr, deg, epak, h1, Wrel2, Wroot2, brel2, h2, (uint32*)0);
    // ---- gate + pool ----
    {
        int n4 = N_GRAPHS * HID / 4;
        zero_f4_kernel<<<(n4 + 255) / 256, 256>>>((float4*)pool, n4);
        gate_pool_kernel<<<nodeBlocks, 256>>>(h2, x, Wsig, Wtanh, bsig, btanh, batch, pool);
    }
    // ---- head ----
    head_kernel<<<N_GRAPHS, 256>>>(pool, Wf1, bf1, Wf2, bf2, Wout, bout, out);
}

// round 14
// speedup vs baseline: 1.2375x; 1.1011x over previous
#include <cuda_runtime.h>
#include <cuda_bf16.h>
#include <math.h>
#include <stdint.h>

#define N_NODES   100000
#define N_EDGES   1600000
#define N_GRAPHS  256
#define IN_DIM    64
#define HID       128
#define RELU_COEF 0.05f

typedef unsigned long long ull;
typedef unsigned int uint32;

// ---------------- scratch (no allocation allowed) ----------------
__device__ float  g_agg1[(size_t)N_NODES * IN_DIM];
__device__ float  g_agg2[(size_t)N_NODES * HID];
__device__ float  g_h1  [(size_t)N_NODES * HID];
__device__ float  g_h2  [(size_t)N_NODES * HID];
__device__ uint32 g_xb  [(size_t)N_NODES * IN_DIM / 2];   // x as bf16x2
__device__ uint32 g_h1b [(size_t)N_NODES * HID / 2];      // h1 as bf16x2
__device__ float  g_pool[N_GRAPHS * HID];
__device__ int    g_deg   [N_NODES];
__device__ int    g_rowptr[N_NODES];
__device__ int    g_fill  [N_NODES];
__device__ int2   g_epak  [N_EDGES];    // (src, bits(w)) sorted by dst
__device__ int    g_blksum[512];

__device__ __forceinline__ float lrelu(float v) {
    return v > 0.f ? v : RELU_COEF * v;
}

// packed f32x2 helpers (sm_100+): 2 fp32 FMAs per issue, bit-exact fp32
#define FMA2(acc, a, b) asm("fma.rn.f32x2 %0, %1, %2, %0;" : "+l"(acc) : "l"(a), "l"(b))
#define PACK2(d, x)     asm("mov.b64 %0, {%1, %1};" : "=l"(d) : "f"(x))
#define UNPACK2(lo, hi, v) asm("mov.b64 {%0, %1}, %2;" : "=f"(lo), "=f"(hi) : "l"(v))

#define CP_COMMIT() asm volatile("cp.async.commit_group;" ::: "memory")
#define CP_WAIT0()  asm volatile("cp.async.wait_group 0;" ::: "memory")

__device__ __forceinline__ uint32 smem_u32(const void* p) {
    uint32 a;
    asm("{ .reg .u64 t; cvta.to.shared.u64 t, %1; cvt.u32.u64 %0, t; }" : "=r"(a) : "l"(p));
    return a;
}
__device__ __forceinline__ void cp16(void* dst_smem, const float* src) {
    uint32 d = smem_u32(dst_smem);
    asm volatile("cp.async.ca.shared.global [%0], [%1], 16;" :: "r"(d), "l"(src));
}

__device__ __forceinline__ uint32 pack_bf2(float a, float b) {
    __nv_bfloat162 h = __floats2bfloat162_rn(a, b);
    return *reinterpret_cast<uint32*>(&h);
}
__device__ __forceinline__ float2 unpack_bf2(uint32 v) {
    __nv_bfloat162 h = *reinterpret_cast<__nv_bfloat162*>(&v);
    return __bfloat1622float2(h);
}

// ---------------- small utility kernels ----------------
__global__ void zero_f4_kernel(float4* p, int n4) {
    int i = blockIdx.x * blockDim.x + threadIdx.x;
    if (i < n4) p[i] = make_float4(0.f, 0.f, 0.f, 0.f);
}
__global__ void zero_int_kernel(int* p, int n) {
    int i = blockIdx.x * blockDim.x + threadIdx.x;
    if (i < n) p[i] = 0;
}
__global__ void tobf16_kernel(const float2* __restrict__ in, uint32* __restrict__ out, int n2) {
    int i = blockIdx.x * blockDim.x + threadIdx.x;
    if (i < n2) {
        float2 v = in[i];
        out[i] = pack_bf2(v.x, v.y);
    }
}

// ---------------- CSR build: histogram / scan / fill ----------------
__global__ void hist_kernel(const int* __restrict__ dst, int* __restrict__ deg) {
    int e = blockIdx.x * blockDim.x + threadIdx.x;
    if (e < N_EDGES) atomicAdd(&deg[dst[e]], 1);
}
__global__ void scan1_kernel(const int* __restrict__ deg, int* __restrict__ rowptr,
                             int* __restrict__ blksum) {
    __shared__ int s[256];
    int i = blockIdx.x * 256 + threadIdx.x;
    int v = (i < N_NODES) ? deg[i] : 0;
    s[threadIdx.x] = v;
    __syncthreads();
    for (int off = 1; off < 256; off <<= 1) {
        int t = 0;
        if (threadIdx.x >= off) t = s[threadIdx.x - off];
        __syncthreads();
        s[threadIdx.x] += t;
        __syncthreads();
    }
    if (i < N_NODES) rowptr[i] = s[threadIdx.x] - v;    // exclusive
    if (threadIdx.x == 255) blksum[blockIdx.x] = s[255];
}
__global__ void scan2_kernel(int* blksum, int nblk) {
    __shared__ int s[512];
    int t = threadIdx.x;
    int v = (t < nblk) ? blksum[t] : 0;
    s[t] = v;
    __syncthreads();
    for (int off = 1; off < 512; off <<= 1) {
        int u = (t >= off) ? s[t - off] : 0;
        __syncthreads();
        s[t] += u;
        __syncthreads();
    }
    if (t < nblk) blksum[t] = s[t] - v;   // exclusive
}
__global__ void scan3_kernel(int* __restrict__ rowptr, int* __restrict__ fill,
                             const int* __restrict__ blksum) {
    int i = blockIdx.x * 256 + threadIdx.x;
    if (i < N_NODES) {
        int r = rowptr[i] + blksum[blockIdx.x];
        rowptr[i] = r;
        fill[i] = r;
    }
}
__global__ void fill_kernel(const int* __restrict__ src, const int* __restrict__ dst,
                            const float* __restrict__ w, int* __restrict__ fill,
                            int2* __restrict__ epak) {
    int e = blockIdx.x * blockDim.x + threadIdx.x;
    if (e < N_EDGES) {
        int pos = atomicAdd(&fill[dst[e]], 1);
        epak[pos] = make_int2(src[e], __float_as_int(w[e]));
    }
}

// ---------------- gather aggregation (bf16 input): warp per node ---------
template<int D>
__global__ void __launch_bounds__(256)
gather_kernel(const uint32* __restrict__ xb, const int* __restrict__ rowptr,
              const int* __restrict__ deg, const int2* __restrict__ epak,
              float* __restrict__ agg)
{
    int warp = (blockIdx.x * blockDim.x + threadIdx.x) >> 5;
    int lane = threadIdx.x & 31;
    if (warp >= N_NODES) return;
    int start = rowptr[warp];
    int d = deg[warp];
    if (D == 128) {
        float4 acc = make_float4(0.f, 0.f, 0.f, 0.f);
        int i = 0;
        for (; i + 1 < d; i += 2) {
            int2 p0 = epak[start + i];
            int2 p1 = epak[start + i + 1];
            uint2 u0 = *(const uint2*)(xb + (size_t)p0.x * 64 + lane * 2);
            uint2 u1 = *(const uint2*)(xb + (size_t)p1.x * 64 + lane * 2);
            float w0 = __int_as_float(p0.y), w1 = __int_as_float(p1.y);
            float2 a0 = unpack_bf2(u0.x), b0 = unpack_bf2(u0.y);
            float2 a1 = unpack_bf2(u1.x), b1 = unpack_bf2(u1.y);
            acc.x += w0 * a0.x; acc.y += w0 * a0.y;
            acc.z += w0 * b0.x; acc.w += w0 * b0.y;
            acc.x += w1 * a1.x; acc.y += w1 * a1.y;
            acc.z += w1 * b1.x; acc.w += w1 * b1.y;
        }
        if (i < d) {
            int2 p = epak[start + i];
            float ww = __int_as_float(p.y);
            uint2 u = *(const uint2*)(xb + (size_t)p.x * 64 + lane * 2);
            float2 a = unpack_bf2(u.x), b = unpack_bf2(u.y);
            acc.x += ww * a.x; acc.y += ww * a.y;
            acc.z += ww * b.x; acc.w += ww * b.y;
        }
        *(float4*)(agg + (size_t)warp * 128 + lane * 4) = acc;
    } else {
        float2 acc = make_float2(0.f, 0.f);
        int i = 0;
        for (; i + 1 < d; i += 2) {
            int2 p0 = epak[start + i];
            int2 p1 = epak[start + i + 1];
            uint32 u0 = xb[(size_t)p0.x * 32 + lane];
            uint32 u1 = xb[(size_t)p1.x * 32 + lane];
            float w0 = __int_as_float(p0.y), w1 = __int_as_float(p1.y);
            float2 a0 = unpack_bf2(u0);
            float2 a1 = unpack_bf2(u1);
            acc.x += w0 * a0.x; acc.y += w0 * a0.y;
            acc.x += w1 * a1.x; acc.y += w1 * a1.y;
        }
        if (i < d) {
            int2 p = epak[start + i];
            float ww = __int_as_float(p.y);
            float2 a = unpack_bf2(xb[(size_t)p.x * 32 + lane]);
            acc.x += ww * a.x; acc.y += ww * a.y;
        }
        *(float2*)(agg + (size_t)warp * 64 + lane * 2) = acc;
    }
}

// ---------------- pipelined dual-input linear + leaky (f32x2) ------------
// R2/R9 arithmetic; smem double-buffered; W via cp.async (no reg cost);
// A chunk staged in 8 regs across the compute; ONE barrier per K-chunk.
template<int K1, int K2>
__global__ void __launch_bounds__(256)
linear2_kernel(const float* __restrict__ A1, const float* __restrict__ A2,
               const float* __restrict__ W1, const float* __restrict__ W2,
               const float* __restrict__ bias, float* __restrict__ out,
               uint32* __restrict__ out_bf)
{
    constexpr int K   = K1 + K2;
    constexpr int KC  = 32;
    constexpr int NCH = K / KC;
    extern __shared__ char sm[];
    float (*Ast)[KC][64]  = (float(*)[KC][64])sm;                     // 2 x 8 KB
    float (*Ws)[KC][128]  = (float(*)[KC][128])(sm + 2 * KC * 64 * 4); // 2 x 16 KB

    const int n0  = blockIdx.x * 64;
    const int tid = threadIdx.x;
    const int tj  = tid & 31;
    const int tn  = tid >> 5;

    auto loadA = [&](int kc, float4* va) {
#pragma unroll
        for (int r = 0; r < 2; r++) {
            int i  = tid + r * 256;
            int n  = i >> 3;
            int k4 = (i & 7) << 2;
            int gn = n0 + n, gk = kc + k4;
            float4 v = make_float4(0.f, 0.f, 0.f, 0.f);
            if (gn < N_NODES) {
                const float* p = (gk < K1) ? (A1 + (size_t)gn * K1 + gk)
                                           : (A2 + (size_t)gn * K2 + (gk - K1));
                v = *(const float4*)p;
            }
            va[r] = v;
        }
    };
    auto storeA = [&](int buf, const float4* va) {
#pragma unroll
        for (int r = 0; r < 2; r++) {
            int i  = tid + r * 256;
            int n  = i >> 3;
            int k4 = (i & 7) << 2;
            Ast[buf][k4 + 0][n] = va[r].x; Ast[buf][k4 + 1][n] = va[r].y;
            Ast[buf][k4 + 2][n] = va[r].z; Ast[buf][k4 + 3][n] = va[r].w;
        }
    };
    auto cpW = [&](int kc, int buf) {
#pragma unroll
        for (int r = 0; r < 4; r++) {
            int i  = tid + r * 256;
            int k  = i >> 5;
            int j4 = (i & 31) << 2;
            int gk = kc + k;
            const float* p = (gk < K1) ? (W1 + (size_t)gk * 128 + j4)
                                       : (W2 + (size_t)(gk - K1) * 128 + j4);
            cp16(&Ws[buf][k][j4], p);
        }
    };

    ull acc[4][4];
#pragma unroll
    for (int p = 0; p < 4; p++)
#pragma unroll
        for (int c = 0; c < 4; c++) acc[p][c] = 0ULL;

    // prologue: fill buffer 0
    float4 va[2];
    cpW(0, 0);
    CP_COMMIT();
    loadA(0, va);
    storeA(0, va);
    CP_WAIT0();
    __syncthreads();

    for (int ch = 0; ch < NCH; ch++) {
        const int cur = ch & 1, nxt = cur ^ 1;
        if (ch + 1 < NCH) {
            cpW((ch + 1) * KC, nxt);
            CP_COMMIT();
            loadA((ch + 1) * KC, va);
        }
#pragma unroll 8
        for (int k = 0; k < KC; k++) {
            float4 w4 = *(const float4*)&Ws[cur][k][tj << 2];
            ull wd0, wd1, wd2, wd3;
            PACK2(wd0, w4.x); PACK2(wd1, w4.y); PACK2(wd2, w4.z); PACK2(wd3, w4.w);
            const ull* ap = (const ull*)&Ast[cur][k][tn << 3];
            ull a0 = ap[0], a1 = ap[1], a2 = ap[2], a3 = ap[3];
            FMA2(acc[0][0], a0, wd0); FMA2(acc[0][1], a0, wd1);
            FMA2(acc[0][2], a0, wd2); FMA2(acc[0][3], a0, wd3);
            FMA2(acc[1][0], a1, wd0); FMA2(acc[1][1], a1, wd1);
            FMA2(acc[1][2], a1, wd2); FMA2(acc[1][3], a1, wd3);
            FMA2(acc[2][0], a2, wd0); FMA2(acc[2][1], a2, wd1);
            FMA2(acc[2][2], a2, wd2); FMA2(acc[2][3], a2, wd3);
            FMA2(acc[3][0], a3, wd0); FMA2(acc[3][1], a3, wd1);
            FMA2(acc[3][2], a3, wd2); FMA2(acc[3][3], a3, wd3);
        }
        if (ch + 1 < NCH) {
            storeA(nxt, va);
            CP_WAIT0();
        }
        __syncthreads();
    }

    float4 bv = *(const float4*)(bias + (tj << 2));
#pragma unroll
    for (int p = 0; p < 4; p++) {
        float lo[4], hi[4];
#pragma unroll
        for (int c = 0; c < 4; c++) UNPACK2(lo[c], hi[c], acc[p][c]);
        int nA = n0 + (tn << 3) + 2 * p;
        if (nA < N_NODES) {
            float4 r;
            r.x = lrelu(lo[0] + bv.x); r.y = lrelu(lo[1] + bv.y);
            r.z = lrelu(lo[2] + bv.z); r.w = lrelu(lo[3] + bv.w);
            *(float4*)(out + (size_t)nA * 128 + (tj << 2)) = r;
            if (out_bf) {
                uint2 u;
                u.x = pack_bf2(r.x, r.y);
                u.y = pack_bf2(r.z, r.w);
                *(uint2*)(out_bf + (size_t)nA * 64 + (tj << 1)) = u;
            }
        }
        if (nA + 1 < N_NODES) {
            float4 r;
            r.x = lrelu(hi[0] + bv.x); r.y = lrelu(hi[1] + bv.y);
            r.z = lrelu(hi[2] + bv.z); r.w = lrelu(hi[3] + bv.w);
            *(float4*)(out + (size_t)(nA + 1) * 128 + (tj << 2)) = r;
            if (out_bf) {
                uint2 u;
                u.x = pack_bf2(r.x, r.y);
                u.y = pack_bf2(r.z, r.w);
                *(uint2*)(out_bf + (size_t)(nA + 1) * 64 + (tj << 1)) = u;
            }
        }
    }
}

// ---------------- pipelined gate + graph pooling (f32x2) -----------------
__global__ void __launch_bounds__(256)
gate_pool_kernel(const float* __restrict__ h2, const float* __restrict__ x0,
                 const float* __restrict__ Wsig, const float* __restrict__ Wtanh,
                 const float* __restrict__ bsig, const float* __restrict__ btanh,
                 const int*   __restrict__ batch, float* __restrict__ pool)
{
    constexpr int K1  = HID;
    constexpr int K2  = IN_DIM;
    constexpr int K   = K1 + K2;   // 192
    constexpr int KC  = 32;
    constexpr int NCH = K / KC;    // 6
    extern __shared__ char sm[];
    float (*Ast)[KC][64]  = (float(*)[KC][64])sm;                          // 2 x 8 KB
    float (*WsS)[KC][128] = (float(*)[KC][128])(sm + 2 * KC * 64 * 4);     // 2 x 16 KB
    float (*WsT)[KC][128] = (float(*)[KC][128])(sm + 2 * KC * 64 * 4 + 2 * KC * 128 * 4);

    const int n0  = blockIdx.x * 64;
    const int tid = threadIdx.x;
    const int tj  = tid & 31;
    const int tn  = tid >> 5;

    auto loadA = [&](int kc, float4* va) {
#pragma unroll
        for (int r = 0; r < 2; r++) {
            int i  = tid + r * 256;
            int n  = i >> 3;
            int k4 = (i & 7) << 2;
            int gn = n0 + n, gk = kc + k4;
            float4 v = make_float4(0.f, 0.f, 0.f, 0.f);
            if (gn < N_NODES) {
                const float* p = (gk < K1) ? (h2 + (size_t)gn * K1 + gk)
                                           : (x0 + (size_t)gn * K2 + (gk - K1));
                v = *(const float4*)p;
            }
            va[r] = v;
        }
    };
    auto storeA = [&](int buf, const float4* va) {
#pragma unroll
        for (int r = 0; r < 2; r++) {
            int i  = tid + r * 256;
            int n  = i >> 3;
            int k4 = (i & 7) << 2;
            Ast[buf][k4 + 0][n] = va[r].x; Ast[buf][k4 + 1][n] = va[r].y;
            Ast[buf][k4 + 2][n] = va[r].z; Ast[buf][k4 + 3][n] = va[r].w;
        }
    };
    auto cpW = [&](int kc, int buf) {
#pragma unroll
        for (int r = 0; r < 4; r++) {
            int i  = tid + r * 256;
            int k  = i >> 5;
            int j4 = (i & 31) << 2;
            int gk = kc + k;
            cp16(&WsS[buf][k][j4], Wsig  + (size_t)gk * 128 + j4);
            cp16(&WsT[buf][k][j4], Wtanh + (size_t)gk * 128 + j4);
        }
    };

    ull accS[4][4], accT[4][4];
#pragma unroll
    for (int p = 0; p < 4; p++)
#pragma unroll
        for (int c = 0; c < 4; c++) { accS[p][c] = 0ULL; accT[p][c] = 0ULL; }

    float4 va[2];
    cpW(0, 0);
    CP_COMMIT();
    loadA(0, va);
    storeA(0, va);
    CP_WAIT0();
    __syncthreads();

    for (int ch = 0; ch < NCH; ch++) {
        const int cur = ch & 1, nxt = cur ^ 1;
        if (ch + 1 < NCH) {
            cpW((ch + 1) * KC, nxt);
            CP_COMMIT();
            loadA((ch + 1) * KC, va);
        }
#pragma unroll 4
        for (int k = 0; k < KC; k++) {
            const ull* ap = (const ull*)&Ast[cur][k][tn << 3];
            ull a0 = ap[0], a1 = ap[1], a2 = ap[2], a3 = ap[3];
            {
                float4 w4 = *(const float4*)&WsS[cur][k][tj << 2];
                ull w0, w1, w2, w3;
                PACK2(w0, w4.x); PACK2(w1, w4.y); PACK2(w2, w4.z); PACK2(w3, w4.w);
                FMA2(accS[0][0], a0, w0); FMA2(accS[0][1], a0, w1);
                FMA2(accS[0][2], a0, w2); FMA2(accS[0][3], a0, w3);
                FMA2(accS[1][0], a1, w0); FMA2(accS[1][1], a1, w1);
                FMA2(accS[1][2], a1, w2); FMA2(accS[1][3], a1, w3);
                FMA2(accS[2][0], a2, w0); FMA2(accS[2][1], a2, w1);
                FMA2(accS[2][2], a2, w2); FMA2(accS[2][3], a2, w3);
                FMA2(accS[3][0], a3, w0); FMA2(accS[3][1], a3, w1);
                FMA2(accS[3][2], a3, w2); FMA2(accS[3][3], a3, w3);
            }
            {
                float4 w4 = *(const float4*)&WsT[cur][k][tj << 2];
                ull w0, w1, w2, w3;
                PACK2(w0, w4.x); PACK2(w1, w4.y); PACK2(w2, w4.z); PACK2(w3, w4.w);
                FMA2(accT[0][0], a0, w0); FMA2(accT[0][1], a0, w1);
                FMA2(accT[0][2], a0, w2); FMA2(accT[0][3], a0, w3);
                FMA2(accT[1][0], a1, w0); FMA2(accT[1][1], a1, w1);
                FMA2(accT[1][2], a1, w2); FMA2(accT[1][3], a1, w3);
                FMA2(accT[2][0], a2, w0); FMA2(accT[2][1], a2, w1);
                FMA2(accT[2][2], a2, w2); FMA2(accT[2][3], a2, w3);
                FMA2(accT[3][0], a3, w0); FMA2(accT[3][1], a3, w1);
                FMA2(accT[3][2], a3, w2); FMA2(accT[3][3], a3, w3);
            }
        }
        if (ch + 1 < NCH) {
            storeA(nxt, va);
            CP_WAIT0();
        }
        __syncthreads();
    }

    float4 bs = *(const float4*)(bsig  + (tj << 2));
    float4 bt = *(const float4*)(btanh + (tj << 2));

    float vS[8][4], vT[8][4];
#pragma unroll
    for (int p = 0; p < 4; p++)
#pragma unroll
        for (int c = 0; c < 4; c++) {
            UNPACK2(vS[2 * p][c], vS[2 * p + 1][c], accS[p][c]);
            UNPACK2(vT[2 * p][c], vT[2 * p + 1][c], accT[p][c]);
        }

    const float bsa[4] = {bs.x, bs.y, bs.z, bs.w};
    const float bta[4] = {bt.x, bt.y, bt.z, bt.w};

    // run-length compress consecutive nodes with same batch id (batch sorted)
    int curb = -1;
    float s[4] = {0.f, 0.f, 0.f, 0.f};
#pragma unroll
    for (int nn = 0; nn < 8; nn++) {
        int n = n0 + (tn << 3) + nn;
        if (n >= N_NODES) break;
        int b = batch[n];
        float v[4];
#pragma unroll
        for (int c = 0; c < 4; c++) {
            float sx = fminf(fmaxf(vS[nn][c] + bsa[c], -30.f), 30.f);
            v[c] = tanhf(vT[nn][c] + bta[c]) / (1.f + expf(sx));
        }
        if (b != curb) {
            if (curb >= 0) {
                float* pp = pool + (size_t)curb * 128 + (tj << 2);
                atomicAdd(pp + 0, s[0]); atomicAdd(pp + 1, s[1]);
                atomicAdd(pp + 2, s[2]); atomicAdd(pp + 3, s[3]);
            }
            curb = b;
            s[0] = v[0]; s[1] = v[1]; s[2] = v[2]; s[3] = v[3];
        } else {
            s[0] += v[0]; s[1] += v[1]; s[2] += v[2]; s[3] += v[3];
        }
    }
    if (curb >= 0) {
        float* pp = pool + (size_t)curb * 128 + (tj << 2);
        atomicAdd(pp + 0, s[0]); atomicAdd(pp + 1, s[1]);
        atomicAdd(pp + 2, s[2]); atomicAdd(pp + 3, s[3]);
    }
}

// ---------------- head MLP: one block per graph ----------------
__global__ void __launch_bounds__(256)
head_kernel(const float* __restrict__ pool,
            const float* __restrict__ Wf1, const float* __restrict__ bf1,
            const float* __restrict__ Wf2, const float* __restrict__ bf2,
            const float* __restrict__ Wout, const float* __restrict__ bout,
            float* __restrict__ out)
{
    __shared__ float p[128], f1[128], f2[258], red[256];
    const int g = blockIdx.x, tid = threadIdx.x;
    if (tid < 128) p[tid] = pool[(size_t)g * 128 + tid];
    __syncthreads();
    if (tid < 128) {
        float s = bf1[tid];
#pragma unroll 8
        for (int k = 0; k < 128; k++) s += p[k] * Wf1[k * 128 + tid];
        f1[tid] = lrelu(s);
    }
    __syncthreads();
    for (int j = tid; j < 258; j += 256) {
        float s = bf2[j];
#pragma unroll 8
        for (int k = 0; k < 128; k++) s += f1[k] * Wf2[k * 258 + j];
        f2[j] = lrelu(s);
    }
    __syncthreads();
    float s = 0.f;
    for (int k = tid; k < 258; k += 256) s += f2[k] * Wout[k];
    red[tid] = s;
    __syncthreads();
    for (int off = 128; off > 0; off >>= 1) {
        if (tid < off) red[tid] += red[tid + off];
        __syncthreads();
    }
    if (tid == 0) {
        float v = red[0] + bout[0];
        out[g] = 1.f / (1.f + expf(-v));
    }
}

// ---------------- launch ----------------
extern "C" void kernel_launch(void* const* d_in, const int* in_sizes, int n_in,
                              void* d_out, int out_size)
{
    const float* x      = (const float*)d_in[0];
    const int*   ei     = (const int*)  d_in[1];
    const int*   batch  = (const int*)  d_in[2];
    const float* eattr  = (const float*)d_in[3];
    const float* Wrel1  = (const float*)d_in[4];
    const float* brel1  = (const float*)d_in[5];
    const float* Wroot1 = (const float*)d_in[6];
    const float* Wrel2  = (const float*)d_in[7];
    const float* brel2  = (const float*)d_in[8];
    const float* Wroot2 = (const float*)d_in[9];
    const float* Wsig   = (const float*)d_in[10];
    const float* bsig   = (const float*)d_in[11];
    const float* Wtanh  = (const float*)d_in[12];
    const float* btanh  = (const float*)d_in[13];
    const float* Wf1    = (const float*)d_in[14];
    const float* bf1    = (const float*)d_in[15];
    const float* Wf2    = (const float*)d_in[16];
    const float* bf2    = (const float*)d_in[17];
    const float* Wout   = (const float*)d_in[18];
    const float* bout   = (const float*)d_in[19];
    float* out = (float*)d_out;

    const int* src = ei;
    const int* dst = ei + N_EDGES;

    float *agg1, *agg2, *h1, *h2, *pool;
    uint32 *xb, *h1b;
    int *deg, *rowptr, *fill, *blksum;
    int2 *epak;
    cudaGetSymbolAddress((void**)&agg1,   g_agg1);
    cudaGetSymbolAddress((void**)&agg2,   g_agg2);
    cudaGetSymbolAddress((void**)&h1,     g_h1);
    cudaGetSymbolAddress((void**)&h2,     g_h2);
    cudaGetSymbolAddress((void**)&xb,     g_xb);
    cudaGetSymbolAddress((void**)&h1b,    g_h1b);
    cudaGetSymbolAddress((void**)&pool,   g_pool);
    cudaGetSymbolAddress((void**)&deg,    g_deg);
    cudaGetSymbolAddress((void**)&rowptr, g_rowptr);
    cudaGetSymbolAddress((void**)&fill,   g_fill);
    cudaGetSymbolAddress((void**)&epak,   g_epak);
    cudaGetSymbolAddress((void**)&blksum, g_blksum);

    const int nodeBlocks = (N_NODES + 63) / 64;
    const int scanBlocks = (N_NODES + 255) / 256;   // 391
    const int edgeBlocks = (N_EDGES + 255) / 256;
    const int SMEM_LIN  = 2 * 8192 + 2 * 16384;     // 49152
    const int SMEM_GATE = 2 * 8192 + 4 * 16384;     // 81920

    static int attrs_set = 0;
    if (!attrs_set) {
        cudaFuncSetAttribute(linear2_kernel<IN_DIM, IN_DIM>,
                             cudaFuncAttributeMaxDynamicSharedMemorySize, SMEM_LIN);
        cudaFuncSetAttribute(linear2_kernel<HID, HID>,
                             cudaFuncAttributeMaxDynamicSharedMemorySize, SMEM_LIN);
        cudaFuncSetAttribute(gate_pool_kernel,
                             cudaFuncAttributeMaxDynamicSharedMemorySize, SMEM_GATE);
        attrs_set = 1;
    }

    // ---- CSR build (shared by both layers) + x -> bf16 ----
    zero_int_kernel<<<scanBlocks, 256>>>(deg, N_NODES);
    hist_kernel<<<edgeBlocks, 256>>>(dst, deg);
    scan1_kernel<<<scanBlocks, 256>>>(deg, rowptr, blksum);
    scan2_kernel<<<1, 512>>>(blksum, scanBlocks);
    scan3_kernel<<<scanBlocks, 256>>>(rowptr, fill, blksum);
    fill_kernel<<<edgeBlocks, 256>>>(src, dst, eattr, fill, epak);
    {
        int n2 = N_NODES * IN_DIM / 2;
        tobf16_kernel<<<(n2 + 255) / 256, 256>>>((const float2*)x, xb, n2);
    }

    // ---- layer 1 ----
    gather_kernel<IN_DIM><<<(N_NODES * 32 + 255) / 256, 256>>>(xb, rowptr, deg, epak, agg1);
    linear2_kernel<IN_DIM, IN_DIM><<<nodeBlocks, 256, SMEM_LIN>>>(agg1, x, Wrel1, Wroot1, brel1, h1, h1b);
    // ---- layer 2 ----
    gather_kernel<HID><<<(N_NODES * 32 + 255) / 256, 256>>>(h1b, rowptr, deg, epak, agg2);
    linear2_kernel<HID, HID><<<nodeBlocks, 256, SMEM_LIN>>>(agg2, h1, Wrel2, Wroot2, brel2, h2, (uint32*)0);
    // ---- gate + pool ----
    {
        int n4 = N_GRAPHS * HID / 4;
        zero_f4_kernel<<<(n4 + 255) / 256, 256>>>((float4*)pool, n4);
        gate_pool_kernel<<<nodeBlocks, 256, SMEM_GATE>>>(h2, x, Wsig, Wtanh, bsig, btanh, batch, pool);
    }
    // ---- head ----
    head_kernel<<<N_GRAPHS, 256>>>(pool, Wf1, bf1, Wf2, bf2, Wout, bout, out);
}

// round 15
// speedup vs baseline: 1.2481x; 1.0085x over previous
#include <cuda_runtime.h>
#include <cuda_bf16.h>
#include <math.h>
#include <stdint.h>

#define N_NODES   100000
#define N_EDGES   1600000
#define N_GRAPHS  256
#define IN_DIM    64
#define HID       128
#define RELU_COEF 0.05f

typedef unsigned long long ull;
typedef unsigned int uint32;

// ---------------- scratch (no allocation allowed) ----------------
__device__ float  g_agg1[(size_t)N_NODES * IN_DIM];
__device__ float  g_agg2[(size_t)N_NODES * HID];
__device__ float  g_h1  [(size_t)N_NODES * HID];
__device__ float  g_h2  [(size_t)N_NODES * HID];
__device__ uint32 g_xb  [(size_t)N_NODES * IN_DIM / 2];   // x as bf16x2
__device__ uint32 g_h1b [(size_t)N_NODES * HID / 2];      // h1 as bf16x2
__device__ float  g_pool[N_GRAPHS * HID];
__device__ int    g_deg   [N_NODES];
__device__ int    g_rowptr[N_NODES];
__device__ int    g_fill  [N_NODES];
__device__ int2   g_epak  [N_EDGES];    // (src, bits(w)) sorted by dst
__device__ int    g_blksum[512];

__device__ __forceinline__ float lrelu(float v) {
    return v > 0.f ? v : RELU_COEF * v;
}

// packed f32x2 helpers (sm_100+): 2 fp32 FMAs per issue, bit-exact fp32
#define FMA2(acc, a, b) asm("fma.rn.f32x2 %0, %1, %2, %0;" : "+l"(acc) : "l"(a), "l"(b))
#define PACK2(d, x)     asm("mov.b64 %0, {%1, %1};" : "=l"(d) : "f"(x))
#define UNPACK2(lo, hi, v) asm("mov.b64 {%0, %1}, %2;" : "=f"(lo), "=f"(hi) : "l"(v))

#define CP_COMMIT() asm volatile("cp.async.commit_group;" ::: "memory")
#define CP_WAIT0()  asm volatile("cp.async.wait_group 0;" ::: "memory")

__device__ __forceinline__ uint32 smem_u32(const void* p) {
    uint32 a;
    asm("{ .reg .u64 t; cvta.to.shared.u64 t, %1; cvt.u32.u64 %0, t; }" : "=r"(a) : "l"(p));
    return a;
}
__device__ __forceinline__ void cp16(void* dst_smem, const float* src) {
    uint32 d = smem_u32(dst_smem);
    asm volatile("cp.async.ca.shared.global [%0], [%1], 16;" :: "r"(d), "l"(src));
}

__device__ __forceinline__ uint32 pack_bf2(float a, float b) {
    __nv_bfloat162 h = __floats2bfloat162_rn(a, b);
    return *reinterpret_cast<uint32*>(&h);
}
__device__ __forceinline__ float2 unpack_bf2(uint32 v) {
    __nv_bfloat162 h = *reinterpret_cast<__nv_bfloat162*>(&v);
    return __bfloat1622float2(h);
}

// ---------------- small utility kernels ----------------
__global__ void zero_f4_kernel(float4* p, int n4) {
    int i = blockIdx.x * blockDim.x + threadIdx.x;
    if (i < n4) p[i] = make_float4(0.f, 0.f, 0.f, 0.f);
}
__global__ void zero_int_kernel(int* p, int n) {
    int i = blockIdx.x * blockDim.x + threadIdx.x;
    if (i < n) p[i] = 0;
}
__global__ void tobf16_kernel(const float2* __restrict__ in, uint32* __restrict__ out, int n2) {
    int i = blockIdx.x * blockDim.x + threadIdx.x;
    if (i < n2) {
        float2 v = in[i];
        out[i] = pack_bf2(v.x, v.y);
    }
}

// ---------------- CSR build: histogram / scan / fill ----------------
__global__ void hist_kernel(const int* __restrict__ dst, int* __restrict__ deg) {
    int e = blockIdx.x * blockDim.x + threadIdx.x;
    if (e < N_EDGES) atomicAdd(&deg[dst[e]], 1);
}
__global__ void scan1_kernel(const int* __restrict__ deg, int* __restrict__ rowptr,
                             int* __restrict__ blksum) {
    __shared__ int s[256];
    int i = blockIdx.x * 256 + threadIdx.x;
    int v = (i < N_NODES) ? deg[i] : 0;
    s[threadIdx.x] = v;
    __syncthreads();
    for (int off = 1; off < 256; off <<= 1) {
        int t = 0;
        if (threadIdx.x >= off) t = s[threadIdx.x - off];
        __syncthreads();
        s[threadIdx.x] += t;
        __syncthreads();
    }
    if (i < N_NODES) rowptr[i] = s[threadIdx.x] - v;    // exclusive
    if (threadIdx.x == 255) blksum[blockIdx.x] = s[255];
}
__global__ void scan2_kernel(int* blksum, int nblk) {
    __shared__ int s[512];
    int t = threadIdx.x;
    int v = (t < nblk) ? blksum[t] : 0;
    s[t] = v;
    __syncthreads();
    for (int off = 1; off < 512; off <<= 1) {
        int u = (t >= off) ? s[t - off] : 0;
        __syncthreads();
        s[t] += u;
        __syncthreads();
    }
    if (t < nblk) blksum[t] = s[t] - v;   // exclusive
}
__global__ void scan3_kernel(int* __restrict__ rowptr, int* __restrict__ fill,
                             const int* __restrict__ blksum) {
    int i = blockIdx.x * 256 + threadIdx.x;
    if (i < N_NODES) {
        int r = rowptr[i] + blksum[blockIdx.x];
        rowptr[i] = r;
        fill[i] = r;
    }
}
__global__ void fill_kernel(const int* __restrict__ src, const int* __restrict__ dst,
                            const float* __restrict__ w, int* __restrict__ fill,
                            int2* __restrict__ epak) {
    int e = blockIdx.x * blockDim.x + threadIdx.x;
    if (e < N_EDGES) {
        int pos = atomicAdd(&fill[dst[e]], 1);
        epak[pos] = make_int2(src[e], __float_as_int(w[e]));
    }
}

// ---------------- gather aggregation (bf16 input): warp per node ---------
// 4-way MLP: batch 4 epak loads, then 4 independent row loads, then FMAs.
template<int D>
__global__ void __launch_bounds__(256)
gather_kernel(const uint32* __restrict__ xb, const int* __restrict__ rowptr,
              const int* __restrict__ deg, const int2* __restrict__ epak,
              float* __restrict__ agg)
{
    int warp = (blockIdx.x * blockDim.x + threadIdx.x) >> 5;
    int lane = threadIdx.x & 31;
    if (warp >= N_NODES) return;
    int start = rowptr[warp];
    int d = deg[warp];
    if (D == 128) {
        float4 acc = make_float4(0.f, 0.f, 0.f, 0.f);
        int i = 0;
        for (; i + 3 < d; i += 4) {
            int2 p0 = epak[start + i];
            int2 p1 = epak[start + i + 1];
            int2 p2 = epak[start + i + 2];
            int2 p3 = epak[start + i + 3];
            uint2 u0 = *(const uint2*)(xb + (size_t)p0.x * 64 + lane * 2);
            uint2 u1 = *(const uint2*)(xb + (size_t)p1.x * 64 + lane * 2);
            uint2 u2 = *(const uint2*)(xb + (size_t)p2.x * 64 + lane * 2);
            uint2 u3 = *(const uint2*)(xb + (size_t)p3.x * 64 + lane * 2);
            float w0 = __int_as_float(p0.y), w1 = __int_as_float(p1.y);
            float w2 = __int_as_float(p2.y), w3 = __int_as_float(p3.y);
            float2 a, b;
            a = unpack_bf2(u0.x); b = unpack_bf2(u0.y);
            acc.x += w0 * a.x; acc.y += w0 * a.y; acc.z += w0 * b.x; acc.w += w0 * b.y;
            a = unpack_bf2(u1.x); b = unpack_bf2(u1.y);
            acc.x += w1 * a.x; acc.y += w1 * a.y; acc.z += w1 * b.x; acc.w += w1 * b.y;
            a = unpack_bf2(u2.x); b = unpack_bf2(u2.y);
            acc.x += w2 * a.x; acc.y += w2 * a.y; acc.z += w2 * b.x; acc.w += w2 * b.y;
            a = unpack_bf2(u3.x); b = unpack_bf2(u3.y);
            acc.x += w3 * a.x; acc.y += w3 * a.y; acc.z += w3 * b.x; acc.w += w3 * b.y;
        }
        for (; i < d; i++) {
            int2 p = epak[start + i];
            float ww = __int_as_float(p.y);
            uint2 u = *(const uint2*)(xb + (size_t)p.x * 64 + lane * 2);
            float2 a = unpack_bf2(u.x), b = unpack_bf2(u.y);
            acc.x += ww * a.x; acc.y += ww * a.y;
            acc.z += ww * b.x; acc.w += ww * b.y;
        }
        *(float4*)(agg + (size_t)warp * 128 + lane * 4) = acc;
    } else {
        float2 acc = make_float2(0.f, 0.f);
        int i = 0;
        for (; i + 3 < d; i += 4) {
            int2 p0 = epak[start + i];
            int2 p1 = epak[start + i + 1];
            int2 p2 = epak[start + i + 2];
            int2 p3 = epak[start + i + 3];
            uint32 u0 = xb[(size_t)p0.x * 32 + lane];
            uint32 u1 = xb[(size_t)p1.x * 32 + lane];
            uint32 u2 = xb[(size_t)p2.x * 32 + lane];
            uint32 u3 = xb[(size_t)p3.x * 32 + lane];
            float w0 = __int_as_float(p0.y), w1 = __int_as_float(p1.y);
            float w2 = __int_as_float(p2.y), w3 = __int_as_float(p3.y);
            float2 a;
            a = unpack_bf2(u0); acc.x += w0 * a.x; acc.y += w0 * a.y;
            a = unpack_bf2(u1); acc.x += w1 * a.x; acc.y += w1 * a.y;
            a = unpack_bf2(u2); acc.x += w2 * a.x; acc.y += w2 * a.y;
            a = unpack_bf2(u3); acc.x += w3 * a.x; acc.y += w3 * a.y;
        }
        for (; i < d; i++) {
            int2 p = epak[start + i];
            float ww = __int_as_float(p.y);
            float2 a = unpack_bf2(xb[(size_t)p.x * 32 + lane]);
            acc.x += ww * a.x; acc.y += ww * a.y;
        }
        *(float2*)(agg + (size_t)warp * 64 + lane * 2) = acc;
    }
}

// ---------------- pipelined dual-input linear + leaky (f32x2) ------------
// R14 version (615.6us): smem double-buffered, W via cp.async, one barrier/chunk.
template<int K1, int K2>
__global__ void __launch_bounds__(256)
linear2_kernel(const float* __restrict__ A1, const float* __restrict__ A2,
               const float* __restrict__ W1, const float* __restrict__ W2,
               const float* __restrict__ bias, float* __restrict__ out,
               uint32* __restrict__ out_bf)
{
    constexpr int K   = K1 + K2;
    constexpr int KC  = 32;
    constexpr int NCH = K / KC;
    extern __shared__ char sm[];
    float (*Ast)[KC][64]  = (float(*)[KC][64])sm;                     // 2 x 8 KB
    float (*Ws)[KC][128]  = (float(*)[KC][128])(sm + 2 * KC * 64 * 4); // 2 x 16 KB

    const int n0  = blockIdx.x * 64;
    const int tid = threadIdx.x;
    const int tj  = tid & 31;
    const int tn  = tid >> 5;

    auto loadA = [&](int kc, float4* va) {
#pragma unroll
        for (int r = 0; r < 2; r++) {
            int i  = tid + r * 256;
            int n  = i >> 3;
            int k4 = (i & 7) << 2;
            int gn = n0 + n, gk = kc + k4;
            float4 v = make_float4(0.f, 0.f, 0.f, 0.f);
            if (gn < N_NODES) {
                const float* p = (gk < K1) ? (A1 + (size_t)gn * K1 + gk)
                                           : (A2 + (size_t)gn * K2 + (gk - K1));
                v = *(const float4*)p;
            }
            va[r] = v;
        }
    };
    auto storeA = [&](int buf, const float4* va) {
#pragma unroll
        for (int r = 0; r < 2; r++) {
            int i  = tid + r * 256;
            int n  = i >> 3;
            int k4 = (i & 7) << 2;
            Ast[buf][k4 + 0][n] = va[r].x; Ast[buf][k4 + 1][n] = va[r].y;
            Ast[buf][k4 + 2][n] = va[r].z; Ast[buf][k4 + 3][n] = va[r].w;
        }
    };
    auto cpW = [&](int kc, int buf) {
#pragma unroll
        for (int r = 0; r < 4; r++) {
            int i  = tid + r * 256;
            int k  = i >> 5;
            int j4 = (i & 31) << 2;
            int gk = kc + k;
            const float* p = (gk < K1) ? (W1 + (size_t)gk * 128 + j4)
                                       : (W2 + (size_t)(gk - K1) * 128 + j4);
            cp16(&Ws[buf][k][j4], p);
        }
    };

    ull acc[4][4];
#pragma unroll
    for (int p = 0; p < 4; p++)
#pragma unroll
        for (int c = 0; c < 4; c++) acc[p][c] = 0ULL;

    // prologue: fill buffer 0
    float4 va[2];
    cpW(0, 0);
    CP_COMMIT();
    loadA(0, va);
    storeA(0, va);
    CP_WAIT0();
    __syncthreads();

    for (int ch = 0; ch < NCH; ch++) {
        const int cur = ch & 1, nxt = cur ^ 1;
        if (ch + 1 < NCH) {
            cpW((ch + 1) * KC, nxt);
            CP_COMMIT();
            loadA((ch + 1) * KC, va);
        }
#pragma unroll 8
        for (int k = 0; k < KC; k++) {
            float4 w4 = *(const float4*)&Ws[cur][k][tj << 2];
            ull wd0, wd1, wd2, wd3;
            PACK2(wd0, w4.x); PACK2(wd1, w4.y); PACK2(wd2, w4.z); PACK2(wd3, w4.w);
            const ull* ap = (const ull*)&Ast[cur][k][tn << 3];
            ull a0 = ap[0], a1 = ap[1], a2 = ap[2], a3 = ap[3];
            FMA2(acc[0][0], a0, wd0); FMA2(acc[0][1], a0, wd1);
            FMA2(acc[0][2], a0, wd2); FMA2(acc[0][3], a0, wd3);
            FMA2(acc[1][0], a1, wd0); FMA2(acc[1][1], a1, wd1);
            FMA2(acc[1][2], a1, wd2); FMA2(acc[1][3], a1, wd3);
            FMA2(acc[2][0], a2, wd0); FMA2(acc[2][1], a2, wd1);
            FMA2(acc[2][2], a2, wd2); FMA2(acc[2][3], a2, wd3);
            FMA2(acc[3][0], a3, wd0); FMA2(acc[3][1], a3, wd1);
            FMA2(acc[3][2], a3, wd2); FMA2(acc[3][3], a3, wd3);
        }
        if (ch + 1 < NCH) {
            storeA(nxt, va);
            CP_WAIT0();
        }
        __syncthreads();
    }

    float4 bv = *(const float4*)(bias + (tj << 2));
#pragma unroll
    for (int p = 0; p < 4; p++) {
        float lo[4], hi[4];
#pragma unroll
        for (int c = 0; c < 4; c++) UNPACK2(lo[c], hi[c], acc[p][c]);
        int nA = n0 + (tn << 3) + 2 * p;
        if (nA < N_NODES) {
            float4 r;
            r.x = lrelu(lo[0] + bv.x); r.y = lrelu(lo[1] + bv.y);
            r.z = lrelu(lo[2] + bv.z); r.w = lrelu(lo[3] + bv.w);
            *(float4*)(out + (size_t)nA * 128 + (tj << 2)) = r;
            if (out_bf) {
                uint2 u;
                u.x = pack_bf2(r.x, r.y);
                u.y = pack_bf2(r.z, r.w);
                *(uint2*)(out_bf + (size_t)nA * 64 + (tj << 1)) = u;
            }
        }
        if (nA + 1 < N_NODES) {
            float4 r;
            r.x = lrelu(hi[0] + bv.x); r.y = lrelu(hi[1] + bv.y);
            r.z = lrelu(hi[2] + bv.z); r.w = lrelu(hi[3] + bv.w);
            *(float4*)(out + (size_t)(nA + 1) * 128 + (tj << 2)) = r;
            if (out_bf) {
                uint2 u;
                u.x = pack_bf2(r.x, r.y);
                u.y = pack_bf2(r.z, r.w);
                *(uint2*)(out_bf + (size_t)(nA + 1) * 64 + (tj << 1)) = u;
            }
        }
    }
}

// ---------------- pipelined gate + graph pooling (f32x2) -----------------
__global__ void __launch_bounds__(256)
gate_pool_kernel(const float* __restrict__ h2, const float* __restrict__ x0,
                 const float* __restrict__ Wsig, const float* __restrict__ Wtanh,
                 const float* __restrict__ bsig, const float* __restrict__ btanh,
                 const int*   __restrict__ batch, float* __restrict__ pool)
{
    constexpr int K1  = HID;
    constexpr int K2  = IN_DIM;
    constexpr int K   = K1 + K2;   // 192
    constexpr int KC  = 32;
    constexpr int NCH = K / KC;    // 6
    extern __shared__ char sm[];
    float (*Ast)[KC][64]  = (float(*)[KC][64])sm;                          // 2 x 8 KB
    float (*WsS)[KC][128] = (float(*)[KC][128])(sm + 2 * KC * 64 * 4);     // 2 x 16 KB
    float (*WsT)[KC][128] = (float(*)[KC][128])(sm + 2 * KC * 64 * 4 + 2 * KC * 128 * 4);

    const int n0  = blockIdx.x * 64;
    const int tid = threadIdx.x;
    const int tj  = tid & 31;
    const int tn  = tid >> 5;

    auto loadA = [&](int kc, float4* va) {
#pragma unroll
        for (int r = 0; r < 2; r++) {
            int i  = tid + r * 256;
            int n  = i >> 3;
            int k4 = (i & 7) << 2;
            int gn = n0 + n, gk = kc + k4;
            float4 v = make_float4(0.f, 0.f, 0.f, 0.f);
            if (gn < N_NODES) {
                const float* p = (gk < K1) ? (h2 + (size_t)gn * K1 + gk)
                                           : (x0 + (size_t)gn * K2 + (gk - K1));
                v = *(const float4*)p;
            }
            va[r] = v;
        }
    };
    auto storeA = [&](int buf, const float4* va) {
#pragma unroll
        for (int r = 0; r < 2; r++) {
            int i  = tid + r * 256;
            int n  = i >> 3;
            int k4 = (i & 7) << 2;
            Ast[buf][k4 + 0][n] = va[r].x; Ast[buf][k4 + 1][n] = va[r].y;
            Ast[buf][k4 + 2][n] = va[r].z; Ast[buf][k4 + 3][n] = va[r].w;
        }
    };
    auto cpW = [&](int kc, int buf) {
#pragma unroll
        for (int r = 0; r < 4; r++) {
            int i  = tid + r * 256;
            int k  = i >> 5;
            int j4 = (i & 31) << 2;
            int gk = kc + k;
            cp16(&WsS[buf][k][j4], Wsig  + (size_t)gk * 128 + j4);
            cp16(&WsT[buf][k][j4], Wtanh + (size_t)gk * 128 + j4);
        }
    };

    ull accS[4][4], accT[4][4];
#pragma unroll
    for (int p = 0; p < 4; p++)
#pragma unroll
        for (int c = 0; c < 4; c++) { accS[p][c] = 0ULL; accT[p][c] = 0ULL; }

    float4 va[2];
    cpW(0, 0);
    CP_COMMIT();
    loadA(0, va);
    storeA(0, va);
    CP_WAIT0();
    __syncthreads();

    for (int ch = 0; ch < NCH; ch++) {
        const int cur = ch & 1, nxt = cur ^ 1;
        if (ch + 1 < NCH) {
            cpW((ch + 1) * KC, nxt);
            CP_COMMIT();
            loadA((ch + 1) * KC, va);
        }
#pragma unroll 4
        for (int k = 0; k < KC; k++) {
            const ull* ap = (const ull*)&Ast[cur][k][tn << 3];
            ull a0 = ap[0], a1 = ap[1], a2 = ap[2], a3 = ap[3];
            {
                float4 w4 = *(const float4*)&WsS[cur][k][tj << 2];
                ull w0, w1, w2, w3;
                PACK2(w0, w4.x); PACK2(w1, w4.y); PACK2(w2, w4.z); PACK2(w3, w4.w);
                FMA2(accS[0][0], a0, w0); FMA2(accS[0][1], a0, w1);
                FMA2(accS[0][2], a0, w2); FMA2(accS[0][3], a0, w3);
                FMA2(accS[1][0], a1, w0); FMA2(accS[1][1], a1, w1);
                FMA2(accS[1][2], a1, w2); FMA2(accS[1][3], a1, w3);
                FMA2(accS[2][0], a2, w0); FMA2(accS[2][1], a2, w1);
                FMA2(accS[2][2], a2, w2); FMA2(accS[2][3], a2, w3);
                FMA2(accS[3][0], a3, w0); FMA2(accS[3][1], a3, w1);
                FMA2(accS[3][2], a3, w2); FMA2(accS[3][3], a3, w3);
            }
            {
                float4 w4 = *(const float4*)&WsT[cur][k][tj << 2];
                ull w0, w1, w2, w3;
                PACK2(w0, w4.x); PACK2(w1, w4.y); PACK2(w2, w4.z); PACK2(w3, w4.w);
                FMA2(accT[0][0], a0, w0); FMA2(accT[0][1], a0, w1);
                FMA2(accT[0][2], a0, w2); FMA2(accT[0][3], a0, w3);
                FMA2(accT[1][0], a1, w0); FMA2(accT[1][1], a1, w1);
                FMA2(accT[1][2], a1, w2); FMA2(accT[1][3], a1, w3);
                FMA2(accT[2][0], a2, w0); FMA2(accT[2][1], a2, w1);
                FMA2(accT[2][2], a2, w2); FMA2(accT[2][3], a2, w3);
                FMA2(accT[3][0], a3, w0); FMA2(accT[3][1], a3, w1);
                FMA2(accT[3][2], a3, w2); FMA2(accT[3][3], a3, w3);
            }
        }
        if (ch + 1 < NCH) {
            storeA(nxt, va);
            CP_WAIT0();
        }
        __syncthreads();
    }

    float4 bs = *(const float4*)(bsig  + (tj << 2));
    float4 bt = *(const float4*)(btanh + (tj << 2));

    float vS[8][4], vT[8][4];
#pragma unroll
    for (int p = 0; p < 4; p++)
#pragma unroll
        for (int c = 0; c < 4; c++) {
            UNPACK2(vS[2 * p][c], vS[2 * p + 1][c], accS[p][c]);
            UNPACK2(vT[2 * p][c], vT[2 * p + 1][c], accT[p][c]);
        }

    const float bsa[4] = {bs.x, bs.y, bs.z, bs.w};
    const float bta[4] = {bt.x, bt.y, bt.z, bt.w};

    // run-length compress consecutive nodes with same batch id (batch sorted)
    int curb = -1;
    float s[4] = {0.f, 0.f, 0.f, 0.f};
#pragma unroll
    for (int nn = 0; nn < 8; nn++) {
        int n = n0 + (tn << 3) + nn;
        if (n >= N_NODES) break;
        int b = batch[n];
        float v[4];
#pragma unroll
        for (int c = 0; c < 4; c++) {
            float sx = fminf(fmaxf(vS[nn][c] + bsa[c], -30.f), 30.f);
            v[c] = tanhf(vT[nn][c] + bta[c]) / (1.f + expf(sx));
        }
        if (b != curb) {
            if (curb >= 0) {
                float* pp = pool + (size_t)curb * 128 + (tj << 2);
                atomicAdd(pp + 0, s[0]); atomicAdd(pp + 1, s[1]);
                atomicAdd(pp + 2, s[2]); atomicAdd(pp + 3, s[3]);
            }
            curb = b;
            s[0] = v[0]; s[1] = v[1]; s[2] = v[2]; s[3] = v[3];
        } else {
            s[0] += v[0]; s[1] += v[1]; s[2] += v[2]; s[3] += v[3];
        }
    }
    if (curb >= 0) {
        float* pp = pool + (size_t)curb * 128 + (tj << 2);
        atomicAdd(pp + 0, s[0]); atomicAdd(pp + 1, s[1]);
        atomicAdd(pp + 2, s[2]); atomicAdd(pp + 3, s[3]);
    }
}

// ---------------- head MLP: one block per graph ----------------
__global__ void __launch_bounds__(256)
head_kernel(const float* __restrict__ pool,
            const float* __restrict__ Wf1, const float* __restrict__ bf1,
            const float* __restrict__ Wf2, const float* __restrict__ bf2,
            const float* __restrict__ Wout, const float* __restrict__ bout,
            float* __restrict__ out)
{
    __shared__ float p[128], f1[128], f2[258], red[256];
    const int g = blockIdx.x, tid = threadIdx.x;
    if (tid < 128) p[tid] = pool[(size_t)g * 128 + tid];
    __syncthreads();
    if (tid < 128) {
        float s = bf1[tid];
#pragma unroll 8
        for (int k = 0; k < 128; k++) s += p[k] * Wf1[k * 128 + tid];
        f1[tid] = lrelu(s);
    }
    __syncthreads();
    for (int j = tid; j < 258; j += 256) {
        float s = bf2[j];
#pragma unroll 8
        for (int k = 0; k < 128; k++) s += f1[k] * Wf2[k * 258 + j];
        f2[j] = lrelu(s);
    }
    __syncthreads();
    float s = 0.f;
    for (int k = tid; k < 258; k += 256) s += f2[k] * Wout[k];
    red[tid] = s;
    __syncthreads();
    for (int off = 128; off > 0; off >>= 1) {
        if (tid < off) red[tid] += red[tid + off];
        __syncthreads();
    }
    if (tid == 0) {
        float v = red[0] + bout[0];
        out[g] = 1.f / (1.f + expf(-v));
    }
}

// ---------------- launch ----------------
extern "C" void kernel_launch(void* const* d_in, const int* in_sizes, int n_in,
                              void* d_out, int out_size)
{
    const float* x      = (const float*)d_in[0];
    const int*   ei     = (const int*)  d_in[1];
    const int*   batch  = (const int*)  d_in[2];
    const float* eattr  = (const float*)d_in[3];
    const float* Wrel1  = (const float*)d_in[4];
    const float* brel1  = (const float*)d_in[5];
    const float* Wroot1 = (const float*)d_in[6];
    const float* Wrel2  = (const float*)d_in[7];
    const float* brel2  = (const float*)d_in[8];
    const float* Wroot2 = (const float*)d_in[9];
    const float* Wsig   = (const float*)d_in[10];
    const float* bsig   = (const float*)d_in[11];
    const float* Wtanh  = (const float*)d_in[12];
    const float* btanh  = (const float*)d_in[13];
    const float* Wf1    = (const float*)d_in[14];
    const float* bf1    = (const float*)d_in[15];
    const float* Wf2    = (const float*)d_in[16];
    const float* bf2    = (const float*)d_in[17];
    const float* Wout   = (const float*)d_in[18];
    const float* bout   = (const float*)d_in[19];
    float* out = (float*)d_out;

    const int* src = ei;
    const int* dst = ei + N_EDGES;

    float *agg1, *agg2, *h1, *h2, *pool;
    uint32 *xb, *h1b;
    int *deg, *rowptr, *fill, *blksum;
    int2 *epak;
    cudaGetSymbolAddress((void**)&agg1,   g_agg1);
    cudaGetSymbolAddress((void**)&agg2,   g_agg2);
    cudaGetSymbolAddress((void**)&h1,     g_h1);
    cudaGetSymbolAddress((void**)&h2,     g_h2);
    cudaGetSymbolAddress((void**)&xb,     g_xb);
    cudaGetSymbolAddress((void**)&h1b,    g_h1b);
    cudaGetSymbolAddress((void**)&pool,   g_pool);
    cudaGetSymbolAddress((void**)&deg,    g_deg);
    cudaGetSymbolAddress((void**)&rowptr, g_rowptr);
    cudaGetSymbolAddress((void**)&fill,   g_fill);
    cudaGetSymbolAddress((void**)&epak,   g_epak);
    cudaGetSymbolAddress((void**)&blksum, g_blksum);

    const int nodeBlocks = (N_NODES + 63) / 64;
    const int scanBlocks = (N_NODES + 255) / 256;   // 391
    const int edgeBlocks = (N_EDGES + 255) / 256;
    const int SMEM_LIN  = 2 * 8192 + 2 * 16384;     // 49152
    const int SMEM_GATE = 2 * 8192 + 4 * 16384;     // 81920

    static int attrs_set = 0;
    if (!attrs_set) {
        cudaFuncSetAttribute(linear2_kernel<IN_DIM, IN_DIM>,
                             cudaFuncAttributeMaxDynamicSharedMemorySize, SMEM_LIN);
        cudaFuncSetAttribute(linear2_kernel<HID, HID>,
                             cudaFuncAttributeMaxDynamicSharedMemorySize, SMEM_LIN);
        cudaFuncSetAttribute(gate_pool_kernel,
                             cudaFuncAttributeMaxDynamicSharedMemorySize, SMEM_GATE);
        attrs_set = 1;
    }

    // ---- CSR build (shared by both layers) + x -> bf16 ----
    zero_int_kernel<<<scanBlocks, 256>>>(deg, N_NODES);
    hist_kernel<<<edgeBlocks, 256>>>(dst, deg);
    scan1_kernel<<<scanBlocks, 256>>>(deg, rowptr, blksum);
    scan2_kernel<<<1, 512>>>(blksum, scanBlocks);
    scan3_kernel<<<scanBlocks, 256>>>(rowptr, fill, blksum);
    fill_kernel<<<edgeBlocks, 256>>>(src, dst, eattr, fill, epak);
    {
        int n2 = N_NODES * IN_DIM / 2;
        tobf16_kernel<<<(n2 + 255) / 256, 256>>>((const float2*)x, xb, n2);
    }

    // ---- layer 1 ----
    gather_kernel<IN_DIM><<<(N_NODES * 32 + 255) / 256, 256>>>(xb, rowptr, deg, epak, agg1);
    linear2_kernel<IN_DIM, IN_DIM><<<nodeBlocks, 256, SMEM_LIN>>>(agg1, x, Wrel1, Wroot1, brel1, h1, h1b);
    // ---- layer 2 ----
    gather_kernel<HID><<<(N_NODES * 32 + 255) / 256, 256>>>(h1b, rowptr, deg, epak, agg2);
    linear2_kernel<HID, HID><<<nodeBlocks, 256, SMEM_LIN>>>(agg2, h1, Wrel2, Wroot2, brel2, h2, (uint32*)0);
    // ---- gate + pool ----
    {
        int n4 = N_GRAPHS * HID / 4;
        zero_f4_kernel<<<(n4 + 255) / 256, 256>>>((float4*)pool, n4);
        gate_pool_kernel<<<nodeBlocks, 256, SMEM_GATE>>>(h2, x, Wsig, Wtanh, bsig, btanh, batch, pool);
    }
    // ---- head ----
    head_kernel<<<N_GRAPHS, 256>>>(pool, Wf1, bf1, Wf2, bf2, Wout, bout, out);
}

// round 17
// speedup vs baseline: 1.2525x; 1.0036x over previous
#include <cuda_runtime.h>
#include <cuda_bf16.h>
#include <math.h>
#include <stdint.h>

#define N_NODES   100000
#define N_EDGES   1600000
#define N_GRAPHS  256
#define IN_DIM    64
#define HID       128
#define RELU_COEF 0.05f

typedef unsigned long long ull;
typedef unsigned int uint32;

// ---------------- scratch (no allocation allowed) ----------------
__device__ float  g_agg1[(size_t)N_NODES * IN_DIM];
__device__ float  g_agg2[(size_t)N_NODES * HID];
__device__ float  g_h1  [(size_t)N_NODES * HID];
__device__ float  g_h2  [(size_t)N_NODES * HID];
__device__ uint32 g_xb  [(size_t)N_NODES * IN_DIM / 2];   // x as bf16x2
__device__ uint32 g_h1b [(size_t)N_NODES * HID / 2];      // h1 as bf16x2
__device__ float  g_pool[N_GRAPHS * HID];
__device__ int    g_deg   [N_NODES];
__device__ int    g_rowptr[N_NODES];
__device__ int    g_fill  [N_NODES];
__device__ int2   g_epak  [N_EDGES];    // (src, bits(w)) sorted by dst
__device__ int    g_blksum[512];

__device__ __forceinline__ float lrelu(float v) {
    return v > 0.f ? v : RELU_COEF * v;
}

// packed f32x2 helpers (sm_100+): 2 fp32 FMAs per issue, bit-exact fp32
#define FMA2(acc, a, b) asm("fma.rn.f32x2 %0, %1, %2, %0;" : "+l"(acc) : "l"(a), "l"(b))
#define PACK2(d, x)     asm("mov.b64 %0, {%1, %1};" : "=l"(d) : "f"(x))
#define UNPACK2(lo, hi, v) asm("mov.b64 {%0, %1}, %2;" : "=f"(lo), "=f"(hi) : "l"(v))

#define CP_COMMIT() asm volatile("cp.async.commit_group;" ::: "memory")
#define CP_WAIT0()  asm volatile("cp.async.wait_group 0;" ::: "memory")

__device__ __forceinline__ uint32 smem_u32(const void* p) {
    uint32 a;
    asm("{ .reg .u64 t; cvta.to.shared.u64 t, %1; cvt.u32.u64 %0, t; }" : "=r"(a) : "l"(p));
    return a;
}
__device__ __forceinline__ void cp16(void* dst_smem, const float* src) {
    uint32 d = smem_u32(dst_smem);
    asm volatile("cp.async.ca.shared.global [%0], [%1], 16;" :: "r"(d), "l"(src));
}

__device__ __forceinline__ uint32 pack_bf2(float a, float b) {
    __nv_bfloat162 h = __floats2bfloat162_rn(a, b);
    return *reinterpret_cast<uint32*>(&h);
}
__device__ __forceinline__ float2 unpack_bf2(uint32 v) {
    __nv_bfloat162 h = *reinterpret_cast<__nv_bfloat162*>(&v);
    return __bfloat1622float2(h);
}

// ---------------- small utility kernels ----------------
__global__ void zero_f4_kernel(float4* p, int n4) {
    int i = blockIdx.x * blockDim.x + threadIdx.x;
    if (i < n4) p[i] = make_float4(0.f, 0.f, 0.f, 0.f);
}
__global__ void zero_int_kernel(int* p, int n) {
    int i = blockIdx.x * blockDim.x + threadIdx.x;
    if (i < n) p[i] = 0;
}
__global__ void tobf16_kernel(const float2* __restrict__ in, uint32* __restrict__ out, int n2) {
    int i = blockIdx.x * blockDim.x + threadIdx.x;
    if (i < n2) {
        float2 v = in[i];
        out[i] = pack_bf2(v.x, v.y);
    }
}

// ---------------- CSR build: histogram / scan / fill ----------------
__global__ void hist_kernel(const int* __restrict__ dst, int* __restrict__ deg) {
    int e = blockIdx.x * blockDim.x + threadIdx.x;
    if (e < N_EDGES) atomicAdd(&deg[dst[e]], 1);
}
__global__ void scan1_kernel(const int* __restrict__ deg, int* __restrict__ rowptr,
                             int* __restrict__ blksum) {
    __shared__ int s[256];
    int i = blockIdx.x * 256 + threadIdx.x;
    int v = (i < N_NODES) ? deg[i] : 0;
    s[threadIdx.x] = v;
    __syncthreads();
    for (int off = 1; off < 256; off <<= 1) {
        int t = 0;
        if (threadIdx.x >= off) t = s[threadIdx.x - off];
        __syncthreads();
        s[threadIdx.x] += t;
        __syncthreads();
    }
    if (i < N_NODES) rowptr[i] = s[threadIdx.x] - v;    // exclusive
    if (threadIdx.x == 255) blksum[blockIdx.x] = s[255];
}
__global__ void scan2_kernel(int* blksum, int nblk) {
    __shared__ int s[512];
    int t = threadIdx.x;
    int v = (t < nblk) ? blksum[t] : 0;
    s[t] = v;
    __syncthreads();
    for (int off = 1; off < 512; off <<= 1) {
        int u = (t >= off) ? s[t - off] : 0;
        __syncthreads();
        s[t] += u;
        __syncthreads();
    }
    if (t < nblk) blksum[t] = s[t] - v;   // exclusive
}
__global__ void scan3_kernel(int* __restrict__ rowptr, int* __restrict__ fill,
                             const int* __restrict__ blksum) {
    int i = blockIdx.x * 256 + threadIdx.x;
    if (i < N_NODES) {
        int r = rowptr[i] + blksum[blockIdx.x];
        rowptr[i] = r;
        fill[i] = r;
    }
}
__global__ void fill_kernel(const int* __restrict__ src, const int* __restrict__ dst,
                            const float* __restrict__ w, int* __restrict__ fill,
                            int2* __restrict__ epak) {
    int e = blockIdx.x * blockDim.x + threadIdx.x;
    if (e < N_EDGES) {
        int pos = atomicAdd(&fill[dst[e]], 1);
        epak[pos] = make_int2(src[e], __float_as_int(w[e]));
    }
}

// ---------------- gather aggregation (bf16 input): warp per node ---------
// 4-way MLP: batch 4 epak loads, then 4 independent row loads, then FMAs.
template<int D>
__global__ void __launch_bounds__(256)
gather_kernel(const uint32* __restrict__ xb, const int* __restrict__ rowptr,
              const int* __restrict__ deg, const int2* __restrict__ epak,
              float* __restrict__ agg)
{
    int warp = (blockIdx.x * blockDim.x + threadIdx.x) >> 5;
    int lane = threadIdx.x & 31;
    if (warp >= N_NODES) return;
    int start = rowptr[warp];
    int d = deg[warp];
    if (D == 128) {
        float4 acc = make_float4(0.f, 0.f, 0.f, 0.f);
        int i = 0;
        for (; i + 3 < d; i += 4) {
            int2 p0 = epak[start + i];
            int2 p1 = epak[start + i + 1];
            int2 p2 = epak[start + i + 2];
            int2 p3 = epak[start + i + 3];
            uint2 u0 = *(const uint2*)(xb + (size_t)p0.x * 64 + lane * 2);
            uint2 u1 = *(const uint2*)(xb + (size_t)p1.x * 64 + lane * 2);
            uint2 u2 = *(const uint2*)(xb + (size_t)p2.x * 64 + lane * 2);
            uint2 u3 = *(const uint2*)(xb + (size_t)p3.x * 64 + lane * 2);
            float w0 = __int_as_float(p0.y), w1 = __int_as_float(p1.y);
            float w2 = __int_as_float(p2.y), w3 = __int_as_float(p3.y);
            float2 a, b;
            a = unpack_bf2(u0.x); b = unpack_bf2(u0.y);
            acc.x += w0 * a.x; acc.y += w0 * a.y; acc.z += w0 * b.x; acc.w += w0 * b.y;
            a = unpack_bf2(u1.x); b = unpack_bf2(u1.y);
            acc.x += w1 * a.x; acc.y += w1 * a.y; acc.z += w1 * b.x; acc.w += w1 * b.y;
            a = unpack_bf2(u2.x); b = unpack_bf2(u2.y);
            acc.x += w2 * a.x; acc.y += w2 * a.y; acc.z += w2 * b.x; acc.w += w2 * b.y;
            a = unpack_bf2(u3.x); b = unpack_bf2(u3.y);
            acc.x += w3 * a.x; acc.y += w3 * a.y; acc.z += w3 * b.x; acc.w += w3 * b.y;
        }
        for (; i < d; i++) {
            int2 p = epak[start + i];
            float ww = __int_as_float(p.y);
            uint2 u = *(const uint2*)(xb + (size_t)p.x * 64 + lane * 2);
            float2 a = unpack_bf2(u.x), b = unpack_bf2(u.y);
            acc.x += ww * a.x; acc.y += ww * a.y;
            acc.z += ww * b.x; acc.w += ww * b.y;
        }
        *(float4*)(agg + (size_t)warp * 128 + lane * 4) = acc;
    } else {
        float2 acc = make_float2(0.f, 0.f);
        int i = 0;
        for (; i + 3 < d; i += 4) {
            int2 p0 = epak[start + i];
            int2 p1 = epak[start + i + 1];
            int2 p2 = epak[start + i + 2];
            int2 p3 = epak[start + i + 3];
            uint32 u0 = xb[(size_t)p0.x * 32 + lane];
            uint32 u1 = xb[(size_t)p1.x * 32 + lane];
            uint32 u2 = xb[(size_t)p2.x * 32 + lane];
            uint32 u3 = xb[(size_t)p3.x * 32 + lane];
            float w0 = __int_as_float(p0.y), w1 = __int_as_float(p1.y);
            float w2 = __int_as_float(p2.y), w3 = __int_as_float(p3.y);
            float2 a;
            a = unpack_bf2(u0); acc.x += w0 * a.x; acc.y += w0 * a.y;
            a = unpack_bf2(u1); acc.x += w1 * a.x; acc.y += w1 * a.y;
            a = unpack_bf2(u2); acc.x += w2 * a.x; acc.y += w2 * a.y;
            a = unpack_bf2(u3); acc.x += w3 * a.x; acc.y += w3 * a.y;
        }
        for (; i < d; i++) {
            int2 p = epak[start + i];
            float ww = __int_as_float(p.y);
            float2 a = unpack_bf2(xb[(size_t)p.x * 32 + lane]);
            acc.x += ww * a.x; acc.y += ww * a.y;
        }
        *(float2*)(agg + (size_t)warp * 64 + lane * 2) = acc;
    }
}

// ---------------- pipelined dual-input linear + leaky (f32x2) ------------
// R14 structure; __launch_bounds__(256, 3). Linear has only 16 ull
// accumulators (vs gate's 32) -> expected to fit 84 regs without inner spill.
template<int K1, int K2>
__global__ void __launch_bounds__(256, 3)
linear2_kernel(const float* __restrict__ A1, const float* __restrict__ A2,
               const float* __restrict__ W1, const float* __restrict__ W2,
               const float* __restrict__ bias, float* __restrict__ out,
               uint32* __restrict__ out_bf)
{
    constexpr int K   = K1 + K2;
    constexpr int KC  = 32;
    constexpr int NCH = K / KC;
    extern __shared__ char sm[];
    float (*Ast)[KC][64]  = (float(*)[KC][64])sm;                     // 2 x 8 KB
    float (*Ws)[KC][128]  = (float(*)[KC][128])(sm + 2 * KC * 64 * 4); // 2 x 16 KB

    const int n0  = blockIdx.x * 64;
    const int tid = threadIdx.x;
    const int tj  = tid & 31;
    const int tn  = tid >> 5;

    auto loadA = [&](int kc, float4* va) {
#pragma unroll
        for (int r = 0; r < 2; r++) {
            int i  = tid + r * 256;
            int n  = i >> 3;
            int k4 = (i & 7) << 2;
            int gn = n0 + n, gk = kc + k4;
            float4 v = make_float4(0.f, 0.f, 0.f, 0.f);
            if (gn < N_NODES) {
                const float* p = (gk < K1) ? (A1 + (size_t)gn * K1 + gk)
                                           : (A2 + (size_t)gn * K2 + (gk - K1));
                v = *(const float4*)p;
            }
            va[r] = v;
        }
    };
    auto storeA = [&](int buf, const float4* va) {
#pragma unroll
        for (int r = 0; r < 2; r++) {
            int i  = tid + r * 256;
            int n  = i >> 3;
            int k4 = (i & 7) << 2;
            Ast[buf][k4 + 0][n] = va[r].x; Ast[buf][k4 + 1][n] = va[r].y;
            Ast[buf][k4 + 2][n] = va[r].z; Ast[buf][k4 + 3][n] = va[r].w;
        }
    };
    auto cpW = [&](int kc, int buf) {
#pragma unroll
        for (int r = 0; r < 4; r++) {
            int i  = tid + r * 256;
            int k  = i >> 5;
            int j4 = (i & 31) << 2;
            int gk = kc + k;
            const float* p = (gk < K1) ? (W1 + (size_t)gk * 128 + j4)
                                       : (W2 + (size_t)(gk - K1) * 128 + j4);
            cp16(&Ws[buf][k][j4], p);
        }
    };

    ull acc[4][4];
#pragma unroll
    for (int p = 0; p < 4; p++)
#pragma unroll
        for (int c = 0; c < 4; c++) acc[p][c] = 0ULL;

    // prologue: fill buffer 0
    float4 va[2];
    cpW(0, 0);
    CP_COMMIT();
    loadA(0, va);
    storeA(0, va);
    CP_WAIT0();
    __syncthreads();

    for (int ch = 0; ch < NCH; ch++) {
        const int cur = ch & 1, nxt = cur ^ 1;
        if (ch + 1 < NCH) {
            cpW((ch + 1) * KC, nxt);
            CP_COMMIT();
            loadA((ch + 1) * KC, va);
        }
#pragma unroll 8
        for (int k = 0; k < KC; k++) {
            float4 w4 = *(const float4*)&Ws[cur][k][tj << 2];
            ull wd0, wd1, wd2, wd3;
            PACK2(wd0, w4.x); PACK2(wd1, w4.y); PACK2(wd2, w4.z); PACK2(wd3, w4.w);
            const ull* ap = (const ull*)&Ast[cur][k][tn << 3];
            ull a0 = ap[0], a1 = ap[1], a2 = ap[2], a3 = ap[3];
            FMA2(acc[0][0], a0, wd0); FMA2(acc[0][1], a0, wd1);
            FMA2(acc[0][2], a0, wd2); FMA2(acc[0][3], a0, wd3);
            FMA2(acc[1][0], a1, wd0); FMA2(acc[1][1], a1, wd1);
            FMA2(acc[1][2], a1, wd2); FMA2(acc[1][3], a1, wd3);
            FMA2(acc[2][0], a2, wd0); FMA2(acc[2][1], a2, wd1);
            FMA2(acc[2][2], a2, wd2); FMA2(acc[2][3], a2, wd3);
            FMA2(acc[3][0], a3, wd0); FMA2(acc[3][1], a3, wd1);
            FMA2(acc[3][2], a3, wd2); FMA2(acc[3][3], a3, wd3);
        }
        if (ch + 1 < NCH) {
            storeA(nxt, va);
            CP_WAIT0();
        }
        __syncthreads();
    }

    float4 bv = *(const float4*)(bias + (tj << 2));
#pragma unroll
    for (int p = 0; p < 4; p++) {
        float lo[4], hi[4];
#pragma unroll
        for (int c = 0; c < 4; c++) UNPACK2(lo[c], hi[c], acc[p][c]);
        int nA = n0 + (tn << 3) + 2 * p;
        if (nA < N_NODES) {
            float4 r;
            r.x = lrelu(lo[0] + bv.x); r.y = lrelu(lo[1] + bv.y);
            r.z = lrelu(lo[2] + bv.z); r.w = lrelu(lo[3] + bv.w);
            *(float4*)(out + (size_t)nA * 128 + (tj << 2)) = r;
            if (out_bf) {
                uint2 u;
                u.x = pack_bf2(r.x, r.y);
                u.y = pack_bf2(r.z, r.w);
                *(uint2*)(out_bf + (size_t)nA * 64 + (tj << 1)) = u;
            }
        }
        if (nA + 1 < N_NODES) {
            float4 r;
            r.x = lrelu(hi[0] + bv.x); r.y = lrelu(hi[1] + bv.y);
            r.z = lrelu(hi[2] + bv.z); r.w = lrelu(hi[3] + bv.w);
            *(float4*)(out + (size_t)(nA + 1) * 128 + (tj << 2)) = r;
            if (out_bf) {
                uint2 u;
                u.x = pack_bf2(r.x, r.y);
                u.y = pack_bf2(r.z, r.w);
                *(uint2*)(out_bf + (size_t)(nA + 1) * 64 + (tj << 1)) = u;
            }
        }
    }
}

// ---------------- pipelined gate + graph pooling (f32x2) -----------------
// R14/R15 version unchanged (NO launch_bounds min-blocks: 64 acc regs would spill).
__global__ void __launch_bounds__(256)
gate_pool_kernel(const float* __restrict__ h2, const float* __restrict__ x0,
                 const float* __restrict__ Wsig, const float* __restrict__ Wtanh,
                 const float* __restrict__ bsig, const float* __restrict__ btanh,
                 const int*   __restrict__ batch, float* __restrict__ pool)
{
    constexpr int K1  = HID;
    constexpr int K2  = IN_DIM;
    constexpr int K   = K1 + K2;   // 192
    constexpr int KC  = 32;
    constexpr int NCH = K / KC;    // 6
    extern __shared__ char sm[];
    float (*Ast)[KC][64]  = (float(*)[KC][64])sm;                          // 2 x 8 KB
    float (*WsS)[KC][128] = (float(*)[KC][128])(sm + 2 * KC * 64 * 4);     // 2 x 16 KB
    float (*WsT)[KC][128] = (float(*)[KC][128])(sm + 2 * KC * 64 * 4 + 2 * KC * 128 * 4);

    const int n0  = blockIdx.x * 64;
    const int tid = threadIdx.x;
    const int tj  = tid & 31;
    const int tn  = tid >> 5;

    auto loadA = [&](int kc, float4* va) {
#pragma unroll
        for (int r = 0; r < 2; r++) {
            int i  = tid + r * 256;
            int n  = i >> 3;
            int k4 = (i & 7) << 2;
            int gn = n0 + n, gk = kc + k4;
            float4 v = make_float4(0.f, 0.f, 0.f, 0.f);
            if (gn < N_NODES) {
                const float* p = (gk < K1) ? (h2 + (size_t)gn * K1 + gk)
                                           : (x0 + (size_t)gn * K2 + (gk - K1));
                v = *(const float4*)p;
            }
            va[r] = v;
        }
    };
    auto storeA = [&](int buf, const float4* va) {
#pragma unroll
        for (int r = 0; r < 2; r++) {
            int i  = tid + r * 256;
            int n  = i >> 3;
            int k4 = (i & 7) << 2;
            Ast[buf][k4 + 0][n] = va[r].x; Ast[buf][k4 + 1][n] = va[r].y;
            Ast[buf][k4 + 2][n] = va[r].z; Ast[buf][k4 + 3][n] = va[r].w;
        }
    };
    auto cpW = [&](int kc, int buf) {
#pragma unroll
        for (int r = 0; r < 4; r++) {
            int i  = tid + r * 256;
            int k  = i >> 5;
            int j4 = (i & 31) << 2;
            int gk = kc + k;
            cp16(&WsS[buf][k][j4], Wsig  + (size_t)gk * 128 + j4);
            cp16(&WsT[buf][k][j4], Wtanh + (size_t)gk * 128 + j4);
        }
    };

    ull accS[4][4], accT[4][4];
#pragma unroll
    for (int p = 0; p < 4; p++)
#pragma unroll
        for (int c = 0; c < 4; c++) { accS[p][c] = 0ULL; accT[p][c] = 0ULL; }

    float4 va[2];
    cpW(0, 0);
    CP_COMMIT();
    loadA(0, va);
    storeA(0, va);
    CP_WAIT0();
    __syncthreads();

    for (int ch = 0; ch < NCH; ch++) {
        const int cur = ch & 1, nxt = cur ^ 1;
        if (ch + 1 < NCH) {
            cpW((ch + 1) * KC, nxt);
            CP_COMMIT();
            loadA((ch + 1) * KC, va);
        }
#pragma unroll 4
        for (int k = 0; k < KC; k++) {
            const ull* ap = (const ull*)&Ast[cur][k][tn << 3];
            ull a0 = ap[0], a1 = ap[1], a2 = ap[2], a3 = ap[3];
            {
                float4 w4 = *(const float4*)&WsS[cur][k][tj << 2];
                ull w0, w1, w2, w3;
                PACK2(w0, w4.x); PACK2(w1, w4.y); PACK2(w2, w4.z); PACK2(w3, w4.w);
                FMA2(accS[0][0], a0, w0); FMA2(accS[0][1], a0, w1);
                FMA2(accS[0][2], a0, w2); FMA2(accS[0][3], a0, w3);
                FMA2(accS[1][0], a1, w0); FMA2(accS[1][1], a1, w1);
                FMA2(accS[1][2], a1, w2); FMA2(accS[1][3], a1, w3);
                FMA2(accS[2][0], a2, w0); FMA2(accS[2][1], a2, w1);
                FMA2(accS[2][2], a2, w2); FMA2(accS[2][3], a2, w3);
                FMA2(accS[3][0], a3, w0); FMA2(accS[3][1], a3, w1);
                FMA2(accS[3][2], a3, w2); FMA2(accS[3][3], a3, w3);
            }
            {
                float4 w4 = *(const float4*)&WsT[cur][k][tj << 2];
                ull w0, w1, w2, w3;
                PACK2(w0, w4.x); PACK2(w1, w4.y); PACK2(w2, w4.z); PACK2(w3, w4.w);
                FMA2(accT[0][0], a0, w0); FMA2(accT[0][1], a0, w1);
                FMA2(accT[0][2], a0, w2); FMA2(accT[0][3], a0, w3);
                FMA2(accT[1][0], a1, w0); FMA2(accT[1][1], a1, w1);
                FMA2(accT[1][2], a1, w2); FMA2(accT[1][3], a1, w3);
                FMA2(accT[2][0], a2, w0); FMA2(accT[2][1], a2, w1);
                FMA2(accT[2][2], a2, w2); FMA2(accT[2][3], a2, w3);
                FMA2(accT[3][0], a3, w0); FMA2(accT[3][1], a3, w1);
                FMA2(accT[3][2], a3, w2); FMA2(accT[3][3], a3, w3);
            }
        }
        if (ch + 1 < NCH) {
            storeA(nxt, va);
            CP_WAIT0();
        }
        __syncthreads();
    }

    float4 bs = *(const float4*)(bsig  + (tj << 2));
    float4 bt = *(const float4*)(btanh + (tj << 2));

    float vS[8][4], vT[8][4];
#pragma unroll
    for (int p = 0; p < 4; p++)
#pragma unroll
        for (int c = 0; c < 4; c++) {
            UNPACK2(vS[2 * p][c], vS[2 * p + 1][c], accS[p][c]);
            UNPACK2(vT[2 * p][c], vT[2 * p + 1][c], accT[p][c]);
        }

    const float bsa[4] = {bs.x, bs.y, bs.z, bs.w};
    const float bta[4] = {bt.x, bt.y, bt.z, bt.w};

    // run-length compress consecutive nodes with same batch id (batch sorted)
    int curb = -1;
    float s[4] = {0.f, 0.f, 0.f, 0.f};
#pragma unroll
    for (int nn = 0; nn < 8; nn++) {
        int n = n0 + (tn << 3) + nn;
        if (n >= N_NODES) break;
        int b = batch[n];
        float v[4];
#pragma unroll
        for (int c = 0; c < 4; c++) {
            float sx = fminf(fmaxf(vS[nn][c] + bsa[c], -30.f), 30.f);
            v[c] = tanhf(vT[nn][c] + bta[c]) / (1.f + expf(sx));
        }
        if (b != curb) {
            if (curb >= 0) {
                float* pp = pool + (size_t)curb * 128 + (tj << 2);
                atomicAdd(pp + 0, s[0]); atomicAdd(pp + 1, s[1]);
                atomicAdd(pp + 2, s[2]); atomicAdd(pp + 3, s[3]);
            }
            curb = b;
            s[0] = v[0]; s[1] = v[1]; s[2] = v[2]; s[3] = v[3];
        } else {
            s[0] += v[0]; s[1] += v[1]; s[2] += v[2]; s[3] += v[3];
        }
    }
    if (curb >= 0) {
        float* pp = pool + (size_t)curb * 128 + (tj << 2);
        atomicAdd(pp + 0, s[0]); atomicAdd(pp + 1, s[1]);
        atomicAdd(pp + 2, s[2]); atomicAdd(pp + 3, s[3]);
    }
}

// ---------------- head MLP: one block per graph ----------------
__global__ void __launch_bounds__(256)
head_kernel(const float* __restrict__ pool,
            const float* __restrict__ Wf1, const float* __restrict__ bf1,
            const float* __restrict__ Wf2, const float* __restrict__ bf2,
            const float* __restrict__ Wout, const float* __restrict__ bout,
            float* __restrict__ out)
{
    __shared__ float p[128], f1[128], f2[258], red[256];
    const int g = blockIdx.x, tid = threadIdx.x;
    if (tid < 128) p[tid] = pool[(size_t)g * 128 + tid];
    __syncthreads();
    if (tid < 128) {
        float s = bf1[tid];
#pragma unroll 8
        for (int k = 0; k < 128; k++) s += p[k] * Wf1[k * 128 + tid];
        f1[tid] = lrelu(s);
    }
    __syncthreads();
    for (int j = tid; j < 258; j += 256) {
        float s = bf2[j];
#pragma unroll 8
        for (int k = 0; k < 128; k++) s += f1[k] * Wf2[k * 258 + j];
        f2[j] = lrelu(s);
    }
    __syncthreads();
    float s = 0.f;
    for (int k = tid; k < 258; k += 256) s += f2[k] * Wout[k];
    red[tid] = s;
    __syncthreads();
    for (int off = 128; off > 0; off >>= 1) {
        if (tid < off) red[tid] += red[tid + off];
        __syncthreads();
    }
    if (tid == 0) {
        float v = red[0] + bout[0];
        out[g] = 1.f / (1.f + expf(-v));
    }
}

// ---------------- launch ----------------
extern "C" void kernel_launch(void* const* d_in, const int* in_sizes, int n_in,
                              void* d_out, int out_size)
{
    const float* x      = (const float*)d_in[0];
    const int*   ei     = (const int*)  d_in[1];
    const int*   batch  = (const int*)  d_in[2];
    const float* eattr  = (const float*)d_in[3];
    const float* Wrel1  = (const float*)d_in[4];
    const float* brel1  = (const float*)d_in[5];
    const float* Wroot1 = (const float*)d_in[6];
    const float* Wrel2  = (const float*)d_in[7];
    const float* brel2  = (const float*)d_in[8];
    const float* Wroot2 = (const float*)d_in[9];
    const float* Wsig   = (const float*)d_in[10];
    const float* bsig   = (const float*)d_in[11];
    const float* Wtanh  = (const float*)d_in[12];
    const float* btanh  = (const float*)d_in[13];
    const float* Wf1    = (const float*)d_in[14];
    const float* bf1    = (const float*)d_in[15];
    const float* Wf2    = (const float*)d_in[16];
    const float* bf2    = (const float*)d_in[17];
    const float* Wout   = (const float*)d_in[18];
    const float* bout   = (const float*)d_in[19];
    float* out = (float*)d_out;

    const int* src = ei;
    const int* dst = ei + N_EDGES;

    float *agg1, *agg2, *h1, *h2, *pool;
    uint32 *xb, *h1b;
    int *deg, *rowptr, *fill, *blksum;
    int2 *epak;
    cudaGetSymbolAddress((void**)&agg1,   g_agg1);
    cudaGetSymbolAddress((void**)&agg2,   g_agg2);
    cudaGetSymbolAddress((void**)&h1,     g_h1);
    cudaGetSymbolAddress((void**)&h2,     g_h2);
    cudaGetSymbolAddress((void**)&xb,     g_xb);
    cudaGetSymbolAddress((void**)&h1b,    g_h1b);
    cudaGetSymbolAddress((void**)&pool,   g_pool);
    cudaGetSymbolAddress((void**)&deg,    g_deg);
    cudaGetSymbolAddress((void**)&rowptr, g_rowptr);
    cudaGetSymbolAddress((void**)&fill,   g_fill);
    cudaGetSymbolAddress((void**)&epak,   g_epak);
    cudaGetSymbolAddress((void**)&blksum, g_blksum);

    const int nodeBlocks = (N_NODES + 63) / 64;
    const int scanBlocks = (N_NODES + 255) / 256;   // 391
    const int edgeBlocks = (N_EDGES + 255) / 256;
    const int SMEM_LIN  = 2 * 8192 + 2 * 16384;     // 49152
    const int SMEM_GATE = 2 * 8192 + 4 * 16384;     // 81920

    static int attrs_set = 0;
    if (!attrs_set) {
        cudaFuncSetAttribute(linear2_kernel<IN_DIM, IN_DIM>,
                             cudaFuncAttributeMaxDynamicSharedMemorySize, SMEM_LIN);
        cudaFuncSetAttribute(linear2_kernel<HID, HID>,
                             cudaFuncAttributeMaxDynamicSharedMemorySize, SMEM_LIN);
        cudaFuncSetAttribute(gate_pool_kernel,
                             cudaFuncAttributeMaxDynamicSharedMemorySize, SMEM_GATE);
        attrs_set = 1;
    }

    // ---- CSR build (shared by both layers) + x -> bf16 ----
    zero_int_kernel<<<scanBlocks, 256>>>(deg, N_NODES);
    hist_kernel<<<edgeBlocks, 256>>>(dst, deg);
    scan1_kernel<<<scanBlocks, 256>>>(deg, rowptr, blksum);
    scan2_kernel<<<1, 512>>>(blksum, scanBlocks);
    scan3_kernel<<<scanBlocks, 256>>>(rowptr, fill, blksum);
    fill_kernel<<<edgeBlocks, 256>>>(src, dst, eattr, fill, epak);
    {
        int n2 = N_NODES * IN_DIM / 2;
        tobf16_kernel<<<(n2 + 255) / 256, 256>>>((const float2*)x, xb, n2);
    }

    // ---- layer 1 ----
    gather_kernel<IN_DIM><<<(N_NODES * 32 + 255) / 256, 256>>>(xb, rowptr, deg, epak, agg1);
    linear2_kernel<IN_DIM, IN_DIM><<<nodeBlocks, 256, SMEM_LIN>>>(agg1, x, Wrel1, Wroot1, brel1, h1, h1b);
    // ---- layer 2 ----
    gather_kernel<HID><<<(N_NODES * 32 + 255) / 256, 256>>>(h1b, rowptr, deg, epak, agg2);
    linear2_kernel<HID, HID><<<nodeBlocks, 256, SMEM_LIN>>>(agg2, h1, Wrel2, Wroot2, brel2, h2, (uint32*)0);
    // ---- gate + pool ----
    {
        int n4 = N_GRAPHS * HID / 4;
        zero_f4_kernel<<<(n4 + 255) / 256, 256>>>((float4*)pool, n4);
        gate_pool_kernel<<<nodeBlocks, 256, SMEM_GATE>>>(h2, x, Wsig, Wtanh, bsig, btanh, batch, pool);
    }
    // ---- head ----
    head_kernel<<<N_GRAPHS, 256>>>(pool, Wf1, bf1, Wf2, bf2, Wout, bout, out);
}